// round 3
// baseline (speedup 1.0000x reference)
#include <cuda_runtime.h>
#include <cuda_bf16.h>
#include <math.h>

// GPTNet: N=128, T=32, V=25, C=256, IC=64, S=3.  B = N*T*V = 102400 rows.
// Pure fp32, 13 launches, graph-capturable, allocation-free (scratch = device globals).

#define NN 128
#define TT 32
#define VV 25
#define CC 256
#define ICC 64
#define SS 3
#define BROWS (NN*TT*VV)

// -------- scratch (reused across phases; all launches are in-order on the
// default stream, so WAR hazards between phases are ordered by the stream) ----
// Q/K layouts: spatial [n][s][v][t*64+c] (inner 2048); temporal [n][s][t][v*64+c] (inner 1600)
__device__ float g_QA  [NN*SS*VV*TT*ICC];        // 78.6 MB  (spatial Q, then tf Q, then tb Q)
__device__ float g_KA  [NN*SS*VV*TT*ICC];        // 78.6 MB
__device__ float g_ATTS[NN*SS*VV*VV];
__device__ float g_ATTF[NN*SS*TT*TT];
__device__ float g_ATTB[NN*SS*TT*TT];
__device__ float g_P768A[(size_t)BROWS*768];     // Y768, later Z768F   (314 MB)
__device__ float g_P768B[(size_t)BROWS*768];     // Z768B               (314 MB)
__device__ float g_Y    [(size_t)BROWS*256];
__device__ float g_ZFln [(size_t)BROWS*256];
__device__ float g_Z    [(size_t)BROWS*256];

__device__ __forceinline__ float gelu_f(float x) {
    return 0.5f * x * (1.0f + erff(x * 0.70710678118654752f));
}

// ---------------------------------------------------------------------------
// K1: in-projection  out = elu(A[Bx256] @ W[256x384] + b) + 1, scattered Q/K.
// MODE 0: spatial layout;  MODE 1: temporal layout.
// BM=64 BN=128 BK=16, 256 thr, micro 4x8.
// ---------------------------------------------------------------------------
template<int MODE>
__global__ void __launch_bounds__(256, 2) gemm_act_kernel(
    const float* __restrict__ A, const float* __restrict__ W,
    const float* __restrict__ bias, float* __restrict__ Qb, float* __restrict__ Kb)
{
    __shared__ __align__(16) float As[16][64];
    __shared__ __align__(16) float Ws[16][128];
    const int tid  = threadIdx.x;
    const int row0 = blockIdx.x * 64;
    const int col0 = blockIdx.y * 128;
    const int tm = tid >> 4, tc = tid & 15;

    float acc[4][8];
#pragma unroll
    for (int i = 0; i < 4; i++)
#pragma unroll
        for (int j = 0; j < 8; j++) acc[i][j] = 0.f;

    const int lam = tid >> 2, lak = (tid & 3) * 4;
    const int lwk = tid >> 4, lwc = (tid & 15) * 4;
    const float* Arow = A + (size_t)(row0 + lam) * 256;

    for (int kb = 0; kb < 256; kb += 16) {
        float4 a4 = *(const float4*)(Arow + kb + lak);
        As[lak + 0][lam] = a4.x; As[lak + 1][lam] = a4.y;
        As[lak + 2][lam] = a4.z; As[lak + 3][lam] = a4.w;
        const float* wr = W + (size_t)(kb + lwk) * 384 + col0;
        *(float4*)&Ws[lwk][lwc]      = *(const float4*)(wr + lwc);
        *(float4*)&Ws[lwk][lwc + 64] = *(const float4*)(wr + lwc + 64);
        __syncthreads();
#pragma unroll
        for (int kk = 0; kk < 16; kk++) {
            float4 a  = *(const float4*)&As[kk][tm * 4];
            float4 w0 = *(const float4*)&Ws[kk][tc * 8];
            float4 w1 = *(const float4*)&Ws[kk][tc * 8 + 4];
            float av[4] = {a.x, a.y, a.z, a.w};
            float wv[8] = {w0.x, w0.y, w0.z, w0.w, w1.x, w1.y, w1.z, w1.w};
#pragma unroll
            for (int i = 0; i < 4; i++)
#pragma unroll
                for (int j = 0; j < 8; j++) acc[i][j] += av[i] * wv[j];
        }
        __syncthreads();
    }

#pragma unroll
    for (int i = 0; i < 4; i++) {
        int r = row0 + tm * 4 + i;
        int n = r / (TT * VV);
        int rem = r % (TT * VV);
        int t = rem / VV, v = rem % VV;
#pragma unroll
        for (int j = 0; j < 8; j++) {
            int jg = col0 + tc * 8 + j;
            float val = acc[i][j] + bias[jg];
            val = (val > 0.f) ? (val + 1.f) : expf(val);   // elu(x)+1
            int c  = jg / 6, ss = jg % 6;
            int s  = (ss < 3) ? ss : ss - 3;
            float* dst = (ss < 3) ? Qb : Kb;
            size_t off;
            if (MODE == 0)
                off = ((size_t)(n * 3 + s) * VV + v) * (TT * ICC) + t * ICC + c;
            else
                off = ((size_t)(n * 3 + s) * TT + t) * (VV * ICC) + v * ICC + c;
            dst[off] = val;
        }
    }
}

// ---------------------------------------------------------------------------
// K2: spatial attention scores.  att[n,s,v,u] = sum_{t,c} q*k ; /rowsum ; +att0
// block = (n,s), 640 threads, one (v,u) each.
// ---------------------------------------------------------------------------
__global__ void __launch_bounds__(640) att_spatial_kernel(
    const float* __restrict__ Q, const float* __restrict__ K,
    const float* __restrict__ att0, float* __restrict__ ATTS)
{
    __shared__ __align__(16) float qt[25][68];
    __shared__ __align__(16) float kt[25][68];
    __shared__ float sa[25][26];
    const int tid = threadIdx.x;
    const int ns  = blockIdx.x;
    const int s   = ns % 3;
    const size_t base = (size_t)ns * (VV * TT * ICC);
    const int v = tid / 25, u = tid % 25;
    float acc = 0.f;

    for (int t = 0; t < 32; t++) {
        for (int idx = tid; idx < 3200; idx += 640) {
            int isk = (idx >= 1600);
            int i2 = idx - isk * 1600;
            int vv = i2 >> 6, cc = i2 & 63;
            float val = (isk ? K : Q)[base + vv * 2048 + t * 64 + cc];
            if (isk) kt[vv][cc] = val; else qt[vv][cc] = val;
        }
        __syncthreads();
        if (tid < 625) {
#pragma unroll
            for (int c4 = 0; c4 < 16; c4++) {
                float4 q4 = *(const float4*)&qt[v][c4 * 4];
                float4 k4 = *(const float4*)&kt[u][c4 * 4];
                acc += q4.x * k4.x + q4.y * k4.y + q4.z * k4.z + q4.w * k4.w;
            }
        }
        __syncthreads();
    }
    if (tid < 625) sa[v][u] = acc;
    __syncthreads();
    if (tid < 625) {
        float sum = 0.f;
#pragma unroll
        for (int uu = 0; uu < 25; uu++) sum += sa[v][uu];
        ATTS[ns * 625 + v * 25 + u] = acc / sum + att0[s * 625 + v * 25 + u];
    }
}

// ---------------------------------------------------------------------------
// K3: y = einsum('nsvu,ntuc->ntvcs', att, x) -> Y768 (col s*256+c).
// block = (n,t), thread = c.
// ---------------------------------------------------------------------------
__global__ void __launch_bounds__(256) y_spatial_kernel(
    const float* __restrict__ ATTS, const float* __restrict__ X,
    float* __restrict__ Y768)
{
    __shared__ __align__(16) float at[3][25][28];
    const int tid = threadIdx.x;
    const int nt  = blockIdx.x;
    const int n   = nt >> 5;
    for (int idx = tid; idx < 3 * 25 * 28; idx += 256) ((float*)at)[idx] = 0.f;
    __syncthreads();
    const float* asrc = ATTS + n * (3 * 625);
    for (int idx = tid; idx < 1875; idx += 256) {
        int s = idx / 625, rr = idx % 625;
        at[s][rr / 25][rr % 25] = asrc[idx];
    }
    float xreg[28];
    xreg[25] = xreg[26] = xreg[27] = 0.f;
    const int c = tid;
    const float* xb = X + (size_t)nt * (VV * CC) + c;
#pragma unroll
    for (int u = 0; u < 25; u++) xreg[u] = xb[u * 256];
    __syncthreads();

    for (int v = 0; v < 25; v++) {
        size_t ro = ((size_t)(nt * VV + v)) * 768 + c;
#pragma unroll
        for (int s = 0; s < 3; s++) {
            const float4* a4 = (const float4*)&at[s][v][0];
            float acc = 0.f;
#pragma unroll
            for (int u4 = 0; u4 < 7; u4++) {
                float4 a = a4[u4];
                acc += a.x * xreg[u4 * 4] + a.y * xreg[u4 * 4 + 1]
                     + a.z * xreg[u4 * 4 + 2] + a.w * xreg[u4 * 4 + 3];
            }
            Y768[ro + s * 256] = acc;
        }
    }
}

// ---------------------------------------------------------------------------
// K4: GEMM (B x KDIM) @ (KDIM x 256) + bias, fused per-row LayerNorm epilogue.
// MODE 0: LN ; 1: gelu(R1+LN) ; 2: gelu(R1+R2+LN).  PERM: W-row perm for
// the s*256+c column layout of A (actual W row = c*3+s).
// BM=64 BN=256 BK=16, 256 thr, micro 4x16.
// ---------------------------------------------------------------------------
template<int KDIM, int MODE, bool PERM>
__global__ void __launch_bounds__(256, 2) gemm_ln_kernel(
    const float* __restrict__ A, const float* __restrict__ W,
    const float* __restrict__ bias,
    const float* __restrict__ R1, const float* __restrict__ R2,
    float* __restrict__ Out)
{
    __shared__ __align__(16) float As[16][64];
    __shared__ __align__(16) float Ws[16][256];
    const int tid  = threadIdx.x;
    const size_t row0 = (size_t)blockIdx.x * 64;
    const int tm = tid >> 4, tc = tid & 15;

    float acc[4][16];
#pragma unroll
    for (int i = 0; i < 4; i++)
#pragma unroll
        for (int j = 0; j < 16; j++) acc[i][j] = 0.f;

    const int lam = tid >> 2, lak = (tid & 3) * 4;
    const int lwk = tid >> 4, lwc = (tid & 15) * 4;
    const float* Arow = A + (row0 + lam) * KDIM;

    for (int kb = 0; kb < KDIM; kb += 16) {
        float4 a4 = *(const float4*)(Arow + kb + lak);
        As[lak + 0][lam] = a4.x; As[lak + 1][lam] = a4.y;
        As[lak + 2][lam] = a4.z; As[lak + 3][lam] = a4.w;
        int k0 = kb + lwk;
        int wsrc = PERM ? ((k0 & 255) * 3 + (k0 >> 8)) : k0;
        const float* wr = W + (size_t)wsrc * 256;
#pragma unroll
        for (int q = 0; q < 4; q++)
            *(float4*)&Ws[lwk][lwc + q * 64] = *(const float4*)(wr + lwc + q * 64);
        __syncthreads();
#pragma unroll
        for (int kk = 0; kk < 16; kk++) {
            float4 a = *(const float4*)&As[kk][tm * 4];
            float av[4] = {a.x, a.y, a.z, a.w};
#pragma unroll
            for (int q = 0; q < 4; q++) {
                float4 w = *(const float4*)&Ws[kk][tc * 16 + q * 4];
#pragma unroll
                for (int i = 0; i < 4; i++) {
                    acc[i][q * 4 + 0] += av[i] * w.x;
                    acc[i][q * 4 + 1] += av[i] * w.y;
                    acc[i][q * 4 + 2] += av[i] * w.z;
                    acc[i][q * 4 + 3] += av[i] * w.w;
                }
            }
        }
        __syncthreads();
    }

    float bs[16];
#pragma unroll
    for (int q = 0; q < 4; q++)
        *(float4*)&bs[q * 4] = *(const float4*)(bias + tc * 16 + q * 4);

#pragma unroll
    for (int i = 0; i < 4; i++) {
        size_t r = row0 + tm * 4 + i;
        float vv[16];
        float sum = 0.f, sq = 0.f;
#pragma unroll
        for (int j = 0; j < 16; j++) {
            float t = acc[i][j] + bs[j];
            vv[j] = t; sum += t; sq += t * t;
        }
#pragma unroll
        for (int m = 8; m >= 1; m >>= 1) {
            sum += __shfl_xor_sync(0xffffffffu, sum, m);
            sq  += __shfl_xor_sync(0xffffffffu, sq,  m);
        }
        float mean = sum * (1.0f / 256.0f);
        float var  = fmaxf(sq * (1.0f / 256.0f) - mean * mean, 0.f);
        float rstd = rsqrtf(var + 1e-5f);
        size_t ro = r * 256 + tc * 16;
        float o[16];
        if (MODE == 0) {
#pragma unroll
            for (int j = 0; j < 16; j++) o[j] = (vv[j] - mean) * rstd;
        } else {
#pragma unroll
            for (int q = 0; q < 4; q++) {
                float4 r1 = *(const float4*)(R1 + ro + q * 4);
                float r1v[4] = {r1.x, r1.y, r1.z, r1.w};
                float r2v[4] = {0.f, 0.f, 0.f, 0.f};
                if (MODE == 2) {
                    float4 r2 = *(const float4*)(R2 + ro + q * 4);
                    r2v[0] = r2.x; r2v[1] = r2.y; r2v[2] = r2.z; r2v[3] = r2.w;
                }
#pragma unroll
                for (int j = 0; j < 4; j++) {
                    float ln = (vv[q * 4 + j] - mean) * rstd;
                    o[q * 4 + j] = gelu_f(r1v[j] + r2v[j] + ln);
                }
            }
        }
#pragma unroll
        for (int q = 0; q < 4; q++)
            *(float4*)(Out + ro + q * 4) = *(float4*)&o[q * 4];
    }
}

// ---------------------------------------------------------------------------
// K5: temporal attention (one direction). a[n,s,t,k]=sum_{v,c} q*k; mask; /rowsum
// block = (n,s), 64 threads, micro 4x4 over 32x32.
// ---------------------------------------------------------------------------
__global__ void __launch_bounds__(64) att_temporal_kernel(
    const float* __restrict__ Q, const float* __restrict__ K,
    float* __restrict__ ATT, int fwd)
{
    __shared__ __align__(16) float qt[32][68];
    __shared__ __align__(16) float kt[32][68];
    const int tid = threadIdx.x;
    const int ns  = blockIdx.x;
    const size_t base = (size_t)ns * (TT * VV * ICC);
    const int ti = tid >> 3, ki = tid & 7;
    float acc[4][4];
#pragma unroll
    for (int i = 0; i < 4; i++)
#pragma unroll
        for (int j = 0; j < 4; j++) acc[i][j] = 0.f;

    const int ltt = tid >> 1;
    const int lcc = (tid & 1) * 32;
    for (int v = 0; v < 25; v++) {
        const float* qsrc = Q + base + ltt * 1600 + v * 64 + lcc;
        const float* ksrc = K + base + ltt * 1600 + v * 64 + lcc;
#pragma unroll
        for (int q8 = 0; q8 < 8; q8++) {
            *(float4*)&qt[ltt][lcc + q8 * 4] = *(const float4*)(qsrc + q8 * 4);
            *(float4*)&kt[ltt][lcc + q8 * 4] = *(const float4*)(ksrc + q8 * 4);
        }
        __syncthreads();
#pragma unroll
        for (int c4 = 0; c4 < 16; c4++) {
            float4 q4[4], k4[4];
#pragma unroll
            for (int i = 0; i < 4; i++) q4[i] = *(const float4*)&qt[ti * 4 + i][c4 * 4];
#pragma unroll
            for (int j = 0; j < 4; j++) k4[j] = *(const float4*)&kt[ki * 4 + j][c4 * 4];
#pragma unroll
            for (int i = 0; i < 4; i++)
#pragma unroll
                for (int j = 0; j < 4; j++)
                    acc[i][j] += q4[i].x * k4[j].x + q4[i].y * k4[j].y
                               + q4[i].z * k4[j].z + q4[i].w * k4[j].w;
        }
        __syncthreads();
    }

#pragma unroll
    for (int i = 0; i < 4; i++) {
        int t = ti * 4 + i;
        float row[4];
        float rsum = 0.f;
#pragma unroll
        for (int j = 0; j < 4; j++) {
            int k = ki * 4 + j;
            bool valid = fwd ? (k <= t) : (k >= t);
            row[j] = valid ? acc[i][j] : 0.f;
            rsum += row[j];
        }
        rsum += __shfl_xor_sync(0xffffffffu, rsum, 1);
        rsum += __shfl_xor_sync(0xffffffffu, rsum, 2);
        rsum += __shfl_xor_sync(0xffffffffu, rsum, 4);
        float inv = 1.f / rsum;
#pragma unroll
        for (int j = 0; j < 4; j++)
            ATT[ns * 1024 + t * 32 + ki * 4 + j] = row[j] * inv;
    }
}

// ---------------------------------------------------------------------------
// K6: z = einsum('nstk,nkvc->ntvcs', a, y) for both directions.
// block = (n,v), thread = c.
// ---------------------------------------------------------------------------
__global__ void __launch_bounds__(256) z_temporal_kernel(
    const float* __restrict__ AF, const float* __restrict__ AB,
    const float* __restrict__ Y, float* __restrict__ ZF, float* __restrict__ ZB)
{
    __shared__ __align__(16) float af[3][32][32];
    __shared__ __align__(16) float ab[3][32][32];
    const int tid = threadIdx.x;
    const int blk = blockIdx.x;
    const int n = blk / 25, v = blk % 25;
    const float* afs = AF + n * 3072;
    const float* abz = AB + n * 3072;
    for (int idx = tid; idx < 3072; idx += 256) {
        ((float*)af)[idx] = afs[idx];
        ((float*)ab)[idx] = abz[idx];
    }
    float yreg[32];
    const int c = tid;
#pragma unroll
    for (int k = 0; k < 32; k++)
        yreg[k] = Y[((size_t)((n * 32 + k) * 25 + v)) * 256 + c];
    __syncthreads();

    for (int t = 0; t < 32; t++) {
        size_t ro = ((size_t)((n * 32 + t) * 25 + v)) * 768;
#pragma unroll
        for (int s = 0; s < 3; s++) {
            const float4* a4 = (const float4*)&af[s][t][0];
            const float4* b4 = (const float4*)&ab[s][t][0];
            float sf = 0.f, sb = 0.f;
#pragma unroll
            for (int k4 = 0; k4 < 8; k4++) {
                float4 a = a4[k4], b = b4[k4];
                sf += a.x * yreg[k4 * 4] + a.y * yreg[k4 * 4 + 1]
                    + a.z * yreg[k4 * 4 + 2] + a.w * yreg[k4 * 4 + 3];
                sb += b.x * yreg[k4 * 4] + b.y * yreg[k4 * 4 + 1]
                    + b.z * yreg[k4 * 4 + 2] + b.w * yreg[k4 * 4 + 3];
            }
            ZF[ro + s * 256 + c] = sf;
            ZB[ro + s * 256 + c] = sb;
        }
    }
}

// ---------------------------------------------------------------------------
extern "C" void kernel_launch(void* const* d_in, const int* in_sizes, int n_in,
                              void* d_out, int out_size)
{
    (void)in_sizes; (void)n_in; (void)out_size;
    const float* x        = (const float*)d_in[0];
    const float* w_in_s   = (const float*)d_in[1];
    const float* b_in_s   = (const float*)d_in[2];
    const float* att0     = (const float*)d_in[3];
    const float* w_out_s  = (const float*)d_in[4];
    const float* b_out_s  = (const float*)d_in[5];
    const float* w_ff_s   = (const float*)d_in[6];
    const float* b_ff_s   = (const float*)d_in[7];
    const float* w_in_tf  = (const float*)d_in[8];
    const float* b_in_tf  = (const float*)d_in[9];
    const float* w_in_tb  = (const float*)d_in[10];
    const float* b_in_tb  = (const float*)d_in[11];
    const float* w_out_tf = (const float*)d_in[12];
    const float* b_out_tf = (const float*)d_in[13];
    const float* w_out_tb = (const float*)d_in[14];
    const float* b_out_tb = (const float*)d_in[15];
    const float* w_ff_t   = (const float*)d_in[16];
    const float* b_ff_t   = (const float*)d_in[17];
    float* out = (float*)d_out;

    float *QA, *KA, *ATTS, *ATTF, *ATTB, *P768A, *P768B, *Y, *ZFln, *Z;
    cudaGetSymbolAddress((void**)&QA,    g_QA);
    cudaGetSymbolAddress((void**)&KA,    g_KA);
    cudaGetSymbolAddress((void**)&ATTS,  g_ATTS);
    cudaGetSymbolAddress((void**)&ATTF,  g_ATTF);
    cudaGetSymbolAddress((void**)&ATTB,  g_ATTB);
    cudaGetSymbolAddress((void**)&P768A, g_P768A);
    cudaGetSymbolAddress((void**)&P768B, g_P768B);
    cudaGetSymbolAddress((void**)&Y,     g_Y);
    cudaGetSymbolAddress((void**)&ZFln,  g_ZFln);
    cudaGetSymbolAddress((void**)&Z,     g_Z);

    const int nblkB = BROWS / 64;            // 1600
    dim3 gA(nblkB, 3);

    // ---- spatial block ----
    gemm_act_kernel<0><<<gA, 256>>>(x, w_in_s, b_in_s, QA, KA);
    att_spatial_kernel<<<NN * SS, 640>>>(QA, KA, att0, ATTS);
    y_spatial_kernel<<<NN * TT, 256>>>(ATTS, x, P768A);                    // Y768
    gemm_ln_kernel<768, 1, true ><<<nblkB, 256>>>(P768A, w_out_s, b_out_s, x, nullptr, Y);
    gemm_ln_kernel<256, 1, false><<<nblkB, 256>>>(Y,     w_ff_s,  b_ff_s,  x, nullptr, Y);

    // ---- temporal block (Q/K buffers reused fwd then bwd) ----
    gemm_act_kernel<1><<<gA, 256>>>(Y, w_in_tf, b_in_tf, QA, KA);
    att_temporal_kernel<<<NN * SS, 64>>>(QA, KA, ATTF, 1);
    gemm_act_kernel<1><<<gA, 256>>>(Y, w_in_tb, b_in_tb, QA, KA);
    att_temporal_kernel<<<NN * SS, 64>>>(QA, KA, ATTB, 0);
    z_temporal_kernel<<<NN * VV, 256>>>(ATTF, ATTB, Y, P768A, P768B);      // Z768F, Z768B
    gemm_ln_kernel<768, 0, true ><<<nblkB, 256>>>(P768A, w_out_tf, b_out_tf, nullptr, nullptr, ZFln);
    gemm_ln_kernel<768, 2, true ><<<nblkB, 256>>>(P768B, w_out_tb, b_out_tb, Y, ZFln, Z);
    gemm_ln_kernel<256, 1, false><<<nblkB, 256>>>(Z,     w_ff_t,   b_ff_t,  Y, nullptr, out);
}

// round 4
// speedup vs baseline: 2.0745x; 2.0745x over previous
#include <cuda_runtime.h>
#include <cuda_bf16.h>
#include <math.h>

// GPTNet: N=128, T=32, V=25, C=256, IC=64, S=3.  B = N*T*V = 102400 rows.
// Pure fp32, 13 launches, graph-capturable, allocation-free (scratch = device globals).
// R4: bank-conflict fixes — W-tile reads remapped to 16B-stride (q*64+tc*4 column
// ownership), As padded to 68 floats/row.

#define NN 128
#define TT 32
#define VV 25
#define CC 256
#define ICC 64
#define SS 3
#define BROWS (NN*TT*VV)

__device__ float g_QA  [NN*SS*VV*TT*ICC];
__device__ float g_KA  [NN*SS*VV*TT*ICC];
__device__ float g_ATTS[NN*SS*VV*VV];
__device__ float g_ATTF[NN*SS*TT*TT];
__device__ float g_ATTB[NN*SS*TT*TT];
__device__ float g_P768A[(size_t)BROWS*768];     // Y768, later Z768F
__device__ float g_P768B[(size_t)BROWS*768];     // Z768B
__device__ float g_Y    [(size_t)BROWS*256];
__device__ float g_ZFln [(size_t)BROWS*256];
__device__ float g_Z    [(size_t)BROWS*256];

__device__ __forceinline__ float gelu_f(float x) {
    return 0.5f * x * (1.0f + erff(x * 0.70710678118654752f));
}

// ---------------------------------------------------------------------------
// K1: in-projection  out = elu(A[Bx256] @ W[256x384] + b) + 1, scattered Q/K.
// Thread (tm,tc) owns rows tm*4..+3, cols {q*64 + tc*4 .. +3} for q=0,1.
// ---------------------------------------------------------------------------
template<int MODE>
__global__ void __launch_bounds__(256, 2) gemm_act_kernel(
    const float* __restrict__ A, const float* __restrict__ W,
    const float* __restrict__ bias, float* __restrict__ Qb, float* __restrict__ Kb)
{
    __shared__ __align__(16) float As[16][68];
    __shared__ __align__(16) float Ws[16][128];
    const int tid  = threadIdx.x;
    const int row0 = blockIdx.x * 64;
    const int col0 = blockIdx.y * 128;
    const int tm = tid >> 4, tc = tid & 15;

    float acc[4][8];
#pragma unroll
    for (int i = 0; i < 4; i++)
#pragma unroll
        for (int j = 0; j < 8; j++) acc[i][j] = 0.f;

    const int lam = tid >> 2, lak = (tid & 3) * 4;
    const int lwk = tid >> 4, lwc = (tid & 15) * 4;
    const float* Arow = A + (size_t)(row0 + lam) * 256;

    for (int kb = 0; kb < 256; kb += 16) {
        float4 a4 = *(const float4*)(Arow + kb + lak);
        As[lak + 0][lam] = a4.x; As[lak + 1][lam] = a4.y;
        As[lak + 2][lam] = a4.z; As[lak + 3][lam] = a4.w;
        const float* wr = W + (size_t)(kb + lwk) * 384 + col0;
        *(float4*)&Ws[lwk][lwc]      = *(const float4*)(wr + lwc);
        *(float4*)&Ws[lwk][lwc + 64] = *(const float4*)(wr + lwc + 64);
        __syncthreads();
#pragma unroll
        for (int kk = 0; kk < 16; kk++) {
            float4 a  = *(const float4*)&As[kk][tm * 4];
            float4 w0 = *(const float4*)&Ws[kk][tc * 4];          // 16B stride, conflict-free
            float4 w1 = *(const float4*)&Ws[kk][tc * 4 + 64];
            float av[4] = {a.x, a.y, a.z, a.w};
            float wv[8] = {w0.x, w0.y, w0.z, w0.w, w1.x, w1.y, w1.z, w1.w};
#pragma unroll
            for (int i = 0; i < 4; i++)
#pragma unroll
                for (int j = 0; j < 8; j++) acc[i][j] += av[i] * wv[j];
        }
        __syncthreads();
    }

#pragma unroll
    for (int i = 0; i < 4; i++) {
        int r = row0 + tm * 4 + i;
        int n = r / (TT * VV);
        int rem = r % (TT * VV);
        int t = rem / VV, v = rem % VV;
#pragma unroll
        for (int q = 0; q < 2; q++) {
#pragma unroll
            for (int jj = 0; jj < 4; jj++) {
                int jg = col0 + q * 64 + tc * 4 + jj;
                float val = acc[i][q * 4 + jj] + bias[jg];
                val = (val > 0.f) ? (val + 1.f) : expf(val);   // elu(x)+1
                int c  = jg / 6, ss = jg % 6;
                int s  = (ss < 3) ? ss : ss - 3;
                float* dst = (ss < 3) ? Qb : Kb;
                size_t off;
                if (MODE == 0)
                    off = ((size_t)(n * 3 + s) * VV + v) * (TT * ICC) + t * ICC + c;
                else
                    off = ((size_t)(n * 3 + s) * TT + t) * (VV * ICC) + v * ICC + c;
                dst[off] = val;
            }
        }
    }
}

// ---------------------------------------------------------------------------
// K2: spatial attention scores.
// ---------------------------------------------------------------------------
__global__ void __launch_bounds__(640) att_spatial_kernel(
    const float* __restrict__ Q, const float* __restrict__ K,
    const float* __restrict__ att0, float* __restrict__ ATTS)
{
    __shared__ __align__(16) float qt[25][68];
    __shared__ __align__(16) float kt[25][68];
    __shared__ float sa[25][26];
    const int tid = threadIdx.x;
    const int ns  = blockIdx.x;
    const int s   = ns % 3;
    const size_t base = (size_t)ns * (VV * TT * ICC);
    const int v = tid / 25, u = tid % 25;
    float acc = 0.f;

    for (int t = 0; t < 32; t++) {
        for (int idx = tid; idx < 3200; idx += 640) {
            int isk = (idx >= 1600);
            int i2 = idx - isk * 1600;
            int vv = i2 >> 6, cc = i2 & 63;
            float val = (isk ? K : Q)[base + vv * 2048 + t * 64 + cc];
            if (isk) kt[vv][cc] = val; else qt[vv][cc] = val;
        }
        __syncthreads();
        if (tid < 625) {
#pragma unroll
            for (int c4 = 0; c4 < 16; c4++) {
                float4 q4 = *(const float4*)&qt[v][c4 * 4];
                float4 k4 = *(const float4*)&kt[u][c4 * 4];
                acc += q4.x * k4.x + q4.y * k4.y + q4.z * k4.z + q4.w * k4.w;
            }
        }
        __syncthreads();
    }
    if (tid < 625) sa[v][u] = acc;
    __syncthreads();
    if (tid < 625) {
        float sum = 0.f;
#pragma unroll
        for (int uu = 0; uu < 25; uu++) sum += sa[v][uu];
        ATTS[ns * 625 + v * 25 + u] = acc / sum + att0[s * 625 + v * 25 + u];
    }
}

// ---------------------------------------------------------------------------
// K3: y = einsum('nsvu,ntuc->ntvcs', att, x) -> Y768 (col s*256+c).
// ---------------------------------------------------------------------------
__global__ void __launch_bounds__(256) y_spatial_kernel(
    const float* __restrict__ ATTS, const float* __restrict__ X,
    float* __restrict__ Y768)
{
    __shared__ __align__(16) float at[3][25][28];
    const int tid = threadIdx.x;
    const int nt  = blockIdx.x;
    const int n   = nt >> 5;
    for (int idx = tid; idx < 3 * 25 * 28; idx += 256) ((float*)at)[idx] = 0.f;
    __syncthreads();
    const float* asrc = ATTS + n * (3 * 625);
    for (int idx = tid; idx < 1875; idx += 256) {
        int s = idx / 625, rr = idx % 625;
        at[s][rr / 25][rr % 25] = asrc[idx];
    }
    float xreg[28];
    xreg[25] = xreg[26] = xreg[27] = 0.f;
    const int c = tid;
    const float* xb = X + (size_t)nt * (VV * CC) + c;
#pragma unroll
    for (int u = 0; u < 25; u++) xreg[u] = xb[u * 256];
    __syncthreads();

    for (int v = 0; v < 25; v++) {
        size_t ro = ((size_t)(nt * VV + v)) * 768 + c;
#pragma unroll
        for (int s = 0; s < 3; s++) {
            const float4* a4 = (const float4*)&at[s][v][0];
            float acc = 0.f;
#pragma unroll
            for (int u4 = 0; u4 < 7; u4++) {
                float4 a = a4[u4];
                acc += a.x * xreg[u4 * 4] + a.y * xreg[u4 * 4 + 1]
                     + a.z * xreg[u4 * 4 + 2] + a.w * xreg[u4 * 4 + 3];
            }
            Y768[ro + s * 256] = acc;
        }
    }
}

// ---------------------------------------------------------------------------
// K4: GEMM (B x KDIM) @ (KDIM x 256) + bias, fused LayerNorm epilogue.
// MODE 0: LN ; 1: gelu(R1+LN) ; 2: gelu(R1+R2+LN).  PERM: W row = c*3+s.
// Thread (tm,tc) owns rows tm*4..+3, cols {q*64 + tc*4 .. +3} for q=0..3.
// ---------------------------------------------------------------------------
template<int KDIM, int MODE, bool PERM>
__global__ void __launch_bounds__(256, 2) gemm_ln_kernel(
    const float* __restrict__ A, const float* __restrict__ W,
    const float* __restrict__ bias,
    const float* __restrict__ R1, const float* __restrict__ R2,
    float* __restrict__ Out)
{
    __shared__ __align__(16) float As[16][68];
    __shared__ __align__(16) float Ws[16][256];
    const int tid  = threadIdx.x;
    const size_t row0 = (size_t)blockIdx.x * 64;
    const int tm = tid >> 4, tc = tid & 15;

    float acc[4][16];
#pragma unroll
    for (int i = 0; i < 4; i++)
#pragma unroll
        for (int j = 0; j < 16; j++) acc[i][j] = 0.f;

    const int lam = tid >> 2, lak = (tid & 3) * 4;
    const int lwk = tid >> 4, lwc = (tid & 15) * 4;
    const float* Arow = A + (row0 + lam) * KDIM;

    for (int kb = 0; kb < KDIM; kb += 16) {
        float4 a4 = *(const float4*)(Arow + kb + lak);
        As[lak + 0][lam] = a4.x; As[lak + 1][lam] = a4.y;
        As[lak + 2][lam] = a4.z; As[lak + 3][lam] = a4.w;
        int k0 = kb + lwk;
        int wsrc = PERM ? ((k0 & 255) * 3 + (k0 >> 8)) : k0;
        const float* wr = W + (size_t)wsrc * 256;
#pragma unroll
        for (int q = 0; q < 4; q++)
            *(float4*)&Ws[lwk][lwc + q * 64] = *(const float4*)(wr + lwc + q * 64);
        __syncthreads();
#pragma unroll
        for (int kk = 0; kk < 16; kk++) {
            float4 a = *(const float4*)&As[kk][tm * 4];
            float av[4] = {a.x, a.y, a.z, a.w};
#pragma unroll
            for (int q = 0; q < 4; q++) {
                float4 w = *(const float4*)&Ws[kk][q * 64 + tc * 4];   // conflict-free
#pragma unroll
                for (int i = 0; i < 4; i++) {
                    acc[i][q * 4 + 0] += av[i] * w.x;
                    acc[i][q * 4 + 1] += av[i] * w.y;
                    acc[i][q * 4 + 2] += av[i] * w.z;
                    acc[i][q * 4 + 3] += av[i] * w.w;
                }
            }
        }
        __syncthreads();
    }

    float bs[16];
#pragma unroll
    for (int q = 0; q < 4; q++)
        *(float4*)&bs[q * 4] = *(const float4*)(bias + q * 64 + tc * 4);

#pragma unroll
    for (int i = 0; i < 4; i++) {
        size_t r = row0 + tm * 4 + i;
        float vv[16];
        float sum = 0.f, sq = 0.f;
#pragma unroll
        for (int j = 0; j < 16; j++) {
            float t = acc[i][j] + bs[j];
            vv[j] = t; sum += t; sq += t * t;
        }
        // 16 lanes sharing tm cover all 256 cols of this row
#pragma unroll
        for (int m = 8; m >= 1; m >>= 1) {
            sum += __shfl_xor_sync(0xffffffffu, sum, m);
            sq  += __shfl_xor_sync(0xffffffffu, sq,  m);
        }
        float mean = sum * (1.0f / 256.0f);
        float var  = fmaxf(sq * (1.0f / 256.0f) - mean * mean, 0.f);
        float rstd = rsqrtf(var + 1e-5f);
        size_t rowbase = r * 256;
#pragma unroll
        for (int q = 0; q < 4; q++) {
            size_t ro = rowbase + q * 64 + tc * 4;
            float o[4];
            if (MODE == 0) {
#pragma unroll
                for (int j = 0; j < 4; j++) o[j] = (vv[q * 4 + j] - mean) * rstd;
            } else {
                float4 r1 = *(const float4*)(R1 + ro);
                float r1v[4] = {r1.x, r1.y, r1.z, r1.w};
                float r2v[4] = {0.f, 0.f, 0.f, 0.f};
                if (MODE == 2) {
                    float4 r2 = *(const float4*)(R2 + ro);
                    r2v[0] = r2.x; r2v[1] = r2.y; r2v[2] = r2.z; r2v[3] = r2.w;
                }
#pragma unroll
                for (int j = 0; j < 4; j++) {
                    float ln = (vv[q * 4 + j] - mean) * rstd;
                    o[j] = gelu_f(r1v[j] + r2v[j] + ln);
                }
            }
            *(float4*)(Out + ro) = *(float4*)&o[0];
        }
    }
}

// ---------------------------------------------------------------------------
// K5: temporal attention (one direction).
// ---------------------------------------------------------------------------
__global__ void __launch_bounds__(64) att_temporal_kernel(
    const float* __restrict__ Q, const float* __restrict__ K,
    float* __restrict__ ATT, int fwd)
{
    __shared__ __align__(16) float qt[32][68];
    __shared__ __align__(16) float kt[32][68];
    const int tid = threadIdx.x;
    const int ns  = blockIdx.x;
    const size_t base = (size_t)ns * (TT * VV * ICC);
    const int ti = tid >> 3, ki = tid & 7;
    float acc[4][4];
#pragma unroll
    for (int i = 0; i < 4; i++)
#pragma unroll
        for (int j = 0; j < 4; j++) acc[i][j] = 0.f;

    const int ltt = tid >> 1;
    const int lcc = (tid & 1) * 32;
    for (int v = 0; v < 25; v++) {
        const float* qsrc = Q + base + ltt * 1600 + v * 64 + lcc;
        const float* ksrc = K + base + ltt * 1600 + v * 64 + lcc;
#pragma unroll
        for (int q8 = 0; q8 < 8; q8++) {
            *(float4*)&qt[ltt][lcc + q8 * 4] = *(const float4*)(qsrc + q8 * 4);
            *(float4*)&kt[ltt][lcc + q8 * 4] = *(const float4*)(ksrc + q8 * 4);
        }
        __syncthreads();
#pragma unroll
        for (int c4 = 0; c4 < 16; c4++) {
            float4 q4[4], k4[4];
#pragma unroll
            for (int i = 0; i < 4; i++) q4[i] = *(const float4*)&qt[ti * 4 + i][c4 * 4];
#pragma unroll
            for (int j = 0; j < 4; j++) k4[j] = *(const float4*)&kt[ki * 4 + j][c4 * 4];
#pragma unroll
            for (int i = 0; i < 4; i++)
#pragma unroll
                for (int j = 0; j < 4; j++)
                    acc[i][j] += q4[i].x * k4[j].x + q4[i].y * k4[j].y
                               + q4[i].z * k4[j].z + q4[i].w * k4[j].w;
        }
        __syncthreads();
    }

#pragma unroll
    for (int i = 0; i < 4; i++) {
        int t = ti * 4 + i;
        float row[4];
        float rsum = 0.f;
#pragma unroll
        for (int j = 0; j < 4; j++) {
            int k = ki * 4 + j;
            bool valid = fwd ? (k <= t) : (k >= t);
            row[j] = valid ? acc[i][j] : 0.f;
            rsum += row[j];
        }
        rsum += __shfl_xor_sync(0xffffffffu, rsum, 1);
        rsum += __shfl_xor_sync(0xffffffffu, rsum, 2);
        rsum += __shfl_xor_sync(0xffffffffu, rsum, 4);
        float inv = 1.f / rsum;
#pragma unroll
        for (int j = 0; j < 4; j++)
            ATT[ns * 1024 + t * 32 + ki * 4 + j] = row[j] * inv;
    }
}

// ---------------------------------------------------------------------------
// K6: z = einsum('nstk,nkvc->ntvcs', a, y) for both directions.
// ---------------------------------------------------------------------------
__global__ void __launch_bounds__(256) z_temporal_kernel(
    const float* __restrict__ AF, const float* __restrict__ AB,
    const float* __restrict__ Y, float* __restrict__ ZF, float* __restrict__ ZB)
{
    __shared__ __align__(16) float af[3][32][32];
    __shared__ __align__(16) float ab[3][32][32];
    const int tid = threadIdx.x;
    const int blk = blockIdx.x;
    const int n = blk / 25, v = blk % 25;
    const float* afs = AF + n * 3072;
    const float* abz = AB + n * 3072;
    for (int idx = tid; idx < 3072; idx += 256) {
        ((float*)af)[idx] = afs[idx];
        ((float*)ab)[idx] = abz[idx];
    }
    float yreg[32];
    const int c = tid;
#pragma unroll
    for (int k = 0; k < 32; k++)
        yreg[k] = Y[((size_t)((n * 32 + k) * 25 + v)) * 256 + c];
    __syncthreads();

    for (int t = 0; t < 32; t++) {
        size_t ro = ((size_t)((n * 32 + t) * 25 + v)) * 768;
#pragma unroll
        for (int s = 0; s < 3; s++) {
            const float4* a4 = (const float4*)&af[s][t][0];
            const float4* b4 = (const float4*)&ab[s][t][0];
            float sf = 0.f, sb = 0.f;
#pragma unroll
            for (int k4 = 0; k4 < 8; k4++) {
                float4 a = a4[k4], b = b4[k4];
                sf += a.x * yreg[k4 * 4] + a.y * yreg[k4 * 4 + 1]
                    + a.z * yreg[k4 * 4 + 2] + a.w * yreg[k4 * 4 + 3];
                sb += b.x * yreg[k4 * 4] + b.y * yreg[k4 * 4 + 1]
                    + b.z * yreg[k4 * 4 + 2] + b.w * yreg[k4 * 4 + 3];
            }
            ZF[ro + s * 256 + c] = sf;
            ZB[ro + s * 256 + c] = sb;
        }
    }
}

// ---------------------------------------------------------------------------
extern "C" void kernel_launch(void* const* d_in, const int* in_sizes, int n_in,
                              void* d_out, int out_size)
{
    (void)in_sizes; (void)n_in; (void)out_size;
    const float* x        = (const float*)d_in[0];
    const float* w_in_s   = (const float*)d_in[1];
    const float* b_in_s   = (const float*)d_in[2];
    const float* att0     = (const float*)d_in[3];
    const float* w_out_s  = (const float*)d_in[4];
    const float* b_out_s  = (const float*)d_in[5];
    const float* w_ff_s   = (const float*)d_in[6];
    const float* b_ff_s   = (const float*)d_in[7];
    const float* w_in_tf  = (const float*)d_in[8];
    const float* b_in_tf  = (const float*)d_in[9];
    const float* w_in_tb  = (const float*)d_in[10];
    const float* b_in_tb  = (const float*)d_in[11];
    const float* w_out_tf = (const float*)d_in[12];
    const float* b_out_tf = (const float*)d_in[13];
    const float* w_out_tb = (const float*)d_in[14];
    const float* b_out_tb = (const float*)d_in[15];
    const float* w_ff_t   = (const float*)d_in[16];
    const float* b_ff_t   = (const float*)d_in[17];
    float* out = (float*)d_out;

    float *QA, *KA, *ATTS, *ATTF, *ATTB, *P768A, *P768B, *Y, *ZFln, *Z;
    cudaGetSymbolAddress((void**)&QA,    g_QA);
    cudaGetSymbolAddress((void**)&KA,    g_KA);
    cudaGetSymbolAddress((void**)&ATTS,  g_ATTS);
    cudaGetSymbolAddress((void**)&ATTF,  g_ATTF);
    cudaGetSymbolAddress((void**)&ATTB,  g_ATTB);
    cudaGetSymbolAddress((void**)&P768A, g_P768A);
    cudaGetSymbolAddress((void**)&P768B, g_P768B);
    cudaGetSymbolAddress((void**)&Y,     g_Y);
    cudaGetSymbolAddress((void**)&ZFln,  g_ZFln);
    cudaGetSymbolAddress((void**)&Z,     g_Z);

    const int nblkB = BROWS / 64;            // 1600
    dim3 gA(nblkB, 3);

    // ---- spatial block ----
    gemm_act_kernel<0><<<gA, 256>>>(x, w_in_s, b_in_s, QA, KA);
    att_spatial_kernel<<<NN * SS, 640>>>(QA, KA, att0, ATTS);
    y_spatial_kernel<<<NN * TT, 256>>>(ATTS, x, P768A);                    // Y768
    gemm_ln_kernel<768, 1, true ><<<nblkB, 256>>>(P768A, w_out_s, b_out_s, x, nullptr, Y);
    gemm_ln_kernel<256, 1, false><<<nblkB, 256>>>(Y,     w_ff_s,  b_ff_s,  x, nullptr, Y);

    // ---- temporal block (Q/K buffers reused fwd then bwd) ----
    gemm_act_kernel<1><<<gA, 256>>>(Y, w_in_tf, b_in_tf, QA, KA);
    att_temporal_kernel<<<NN * SS, 64>>>(QA, KA, ATTF, 1);
    gemm_act_kernel<1><<<gA, 256>>>(Y, w_in_tb, b_in_tb, QA, KA);
    att_temporal_kernel<<<NN * SS, 64>>>(QA, KA, ATTB, 0);
    z_temporal_kernel<<<NN * VV, 256>>>(ATTF, ATTB, Y, P768A, P768B);      // Z768F, Z768B
    gemm_ln_kernel<768, 0, true ><<<nblkB, 256>>>(P768A, w_out_tf, b_out_tf, nullptr, nullptr, ZFln);
    gemm_ln_kernel<768, 2, true ><<<nblkB, 256>>>(P768B, w_out_tb, b_out_tb, Y, ZFln, Z);
    gemm_ln_kernel<256, 1, false><<<nblkB, 256>>>(Z,     w_ff_t,   b_ff_t,  Y, nullptr, out);
}

// round 5
// speedup vs baseline: 2.6353x; 1.2704x over previous
#include <cuda_runtime.h>
#include <cuda_bf16.h>
#include <math.h>

// GPTNet: N=128, T=32, V=25, C=256, IC=64, S=3.  B = N*T*V = 102400 rows.
// R5: dense GEMMs moved to tf32 mma.sync.m16n8k8 (fp32 accumulate).
// 13 launches, graph-capturable, allocation-free.

#define NN 128
#define TT 32
#define VV 25
#define CC 256
#define ICC 64
#define SS 3
#define BROWS (NN*TT*VV)

__device__ float g_QA  [NN*SS*VV*TT*ICC];
__device__ float g_KA  [NN*SS*VV*TT*ICC];
__device__ float g_ATTS[NN*SS*VV*VV];
__device__ float g_ATTF[NN*SS*TT*TT];
__device__ float g_ATTB[NN*SS*TT*TT];
__device__ float g_P768A[(size_t)BROWS*768];     // Y768, later Z768F
__device__ float g_P768B[(size_t)BROWS*768];     // Z768B
__device__ float g_Y    [(size_t)BROWS*256];
__device__ float g_ZFln [(size_t)BROWS*256];
__device__ float g_Z    [(size_t)BROWS*256];

__device__ __forceinline__ float gelu_f(float x) {
    return 0.5f * x * (1.0f + erff(x * 0.70710678118654752f));
}

__device__ __forceinline__ unsigned f2tf(float v) {
    unsigned r;
    asm("cvt.rna.tf32.f32 %0, %1;" : "=r"(r) : "f"(v));
    return r;
}

// d += a(16x8,row) * b(8x8,col), tf32 inputs, fp32 accum
__device__ __forceinline__ void mma16n8k8(float* d, const unsigned* a,
                                          unsigned b0, unsigned b1) {
    asm volatile(
        "mma.sync.aligned.m16n8k8.row.col.f32.tf32.tf32.f32 "
        "{%0,%1,%2,%3}, {%4,%5,%6,%7}, {%8,%9}, {%0,%1,%2,%3};\n"
        : "+f"(d[0]), "+f"(d[1]), "+f"(d[2]), "+f"(d[3])
        : "r"(a[0]), "r"(a[1]), "r"(a[2]), "r"(a[3]), "r"(b0), "r"(b1));
}

// ---------------------------------------------------------------------------
// K1 (tensor): in-projection  out = elu(A[Bx256] @ W[256x384] + b) + 1, scatter.
// BM=64, BN=128 (grid.y=3), 128 thr (4 warps), warp = 16 rows x 128 cols.
// ---------------------------------------------------------------------------
template<int MODE>
__global__ void __launch_bounds__(128) gemm_act_tc(
    const float* __restrict__ A, const float* __restrict__ W,
    const float* __restrict__ bias, float* __restrict__ Qb, float* __restrict__ Kb)
{
    __shared__ __align__(16) unsigned As[64][20];    // stride 20 -> conflict-free frag reads
    __shared__ __align__(16) unsigned Ws[16][136];   // 136 % 32 == 8 -> conflict-free
    const int tid  = threadIdx.x;
    const int wid  = tid >> 5, lane = tid & 31;
    const int g    = lane >> 2, tig = lane & 3;
    const int row0 = blockIdx.x * 64;
    const int col0 = blockIdx.y * 128;
    const int mrow = wid * 16;

    float acc[16][4];
#pragma unroll
    for (int i = 0; i < 16; i++)
#pragma unroll
        for (int j = 0; j < 4; j++) acc[i][j] = 0.f;

    const int ar = tid >> 1;                // 0..63
    const int ak = (tid & 1) * 8;           // 0 or 8
    const float* Arow = A + (size_t)(row0 + ar) * 256 + ak;
    const int wrk = tid >> 3;               // 0..15
    const int wrc = (tid & 7) * 16;         // 0..112

    for (int kb = 0; kb < 256; kb += 16) {
        float4 p = *(const float4*)(Arow + kb);
        float4 q = *(const float4*)(Arow + kb + 4);
        unsigned* as = &As[ar][ak];
        as[0] = f2tf(p.x); as[1] = f2tf(p.y); as[2] = f2tf(p.z); as[3] = f2tf(p.w);
        as[4] = f2tf(q.x); as[5] = f2tf(q.y); as[6] = f2tf(q.z); as[7] = f2tf(q.w);
        const float* wr = W + (size_t)(kb + wrk) * 384 + col0 + wrc;
        unsigned* ws = &Ws[wrk][wrc];
#pragma unroll
        for (int j4 = 0; j4 < 4; j4++) {
            float4 w = *(const float4*)(wr + j4 * 4);
            ws[j4*4+0] = f2tf(w.x); ws[j4*4+1] = f2tf(w.y);
            ws[j4*4+2] = f2tf(w.z); ws[j4*4+3] = f2tf(w.w);
        }
        __syncthreads();
#pragma unroll
        for (int kk = 0; kk < 2; kk++) {
            unsigned af[4];
            af[0] = As[mrow + g    ][kk*8 + tig];
            af[1] = As[mrow + g + 8][kk*8 + tig];
            af[2] = As[mrow + g    ][kk*8 + tig + 4];
            af[3] = As[mrow + g + 8][kk*8 + tig + 4];
#pragma unroll
            for (int ni = 0; ni < 16; ni++) {
                unsigned b0 = Ws[kk*8 + tig    ][ni*8 + g];
                unsigned b1 = Ws[kk*8 + tig + 4][ni*8 + g];
                mma16n8k8(acc[ni], af, b0, b1);
            }
        }
        __syncthreads();
    }

    // epilogue: thread owns rows {rA, rB}, cols col0 + ni*8 + 2*tig + {0,1}
    const int rA = row0 + mrow + g;
    const int rB = rA + 8;
    const int nA = rA / (TT*VV), remA = rA % (TT*VV), tA = remA / VV, vA = remA % VV;
    const int nB = rB / (TT*VV), remB = rB % (TT*VV), tB = remB / VV, vB = remB % VV;

    auto scatter = [&](int rn, int rt, int rv, int jg, float val) {
        val = (val > 0.f) ? (val + 1.f) : expf(val);     // elu(x)+1
        int c = jg / 6, ss = jg % 6;
        int s = (ss < 3) ? ss : ss - 3;
        float* dst = (ss < 3) ? Qb : Kb;
        size_t off;
        if (MODE == 0)
            off = ((size_t)(rn * 3 + s) * VV + rv) * (TT * ICC) + rt * ICC + c;
        else
            off = ((size_t)(rn * 3 + s) * TT + rt) * (VV * ICC) + rv * ICC + c;
        dst[off] = val;
    };

#pragma unroll
    for (int ni = 0; ni < 16; ni++) {
        int jg0 = col0 + ni*8 + tig*2;
        float2 b = *(const float2*)(bias + jg0);
        scatter(nA, tA, vA, jg0,     acc[ni][0] + b.x);
        scatter(nA, tA, vA, jg0 + 1, acc[ni][1] + b.y);
        scatter(nB, tB, vB, jg0,     acc[ni][2] + b.x);
        scatter(nB, tB, vB, jg0 + 1, acc[ni][3] + b.y);
    }
}

// ---------------------------------------------------------------------------
// K4 (tensor): GEMM (B x KDIM) @ (KDIM x 256) + bias, fused LN epilogue.
// MODE 0: LN ; 1: gelu(R1+LN) ; 2: gelu(R1+R2+LN).  PERM: W row = c*3+s.
// BM=64, BN=256, 128 thr (4 warps), warp = 16 rows x 256 cols.
// ---------------------------------------------------------------------------
template<int KDIM, int MODE, bool PERM>
__global__ void __launch_bounds__(128) gemm_ln_tc(
    const float* __restrict__ A, const float* __restrict__ W,
    const float* __restrict__ bias,
    const float* __restrict__ R1, const float* __restrict__ R2,
    float* __restrict__ Out)
{
    __shared__ __align__(16) unsigned As[64][20];
    __shared__ __align__(16) unsigned Ws[16][264];   // 264 % 32 == 8
    const int tid  = threadIdx.x;
    const int wid  = tid >> 5, lane = tid & 31;
    const int g    = lane >> 2, tig = lane & 3;
    const size_t row0 = (size_t)blockIdx.x * 64;
    const int mrow = wid * 16;

    float acc[32][4];
#pragma unroll
    for (int i = 0; i < 32; i++)
#pragma unroll
        for (int j = 0; j < 4; j++) acc[i][j] = 0.f;

    const int ar = tid >> 1;
    const int ak = (tid & 1) * 8;
    const float* Arow = A + (row0 + ar) * KDIM + ak;
    const int lwk = tid >> 4;               // 0..7 -> W rows lwk, lwk+8
    const int lwc = (tid & 15) * 4;         // 0..60

    for (int kb = 0; kb < KDIM; kb += 16) {
        float4 p = *(const float4*)(Arow + kb);
        float4 q = *(const float4*)(Arow + kb + 4);
        unsigned* as = &As[ar][ak];
        as[0] = f2tf(p.x); as[1] = f2tf(p.y); as[2] = f2tf(p.z); as[3] = f2tf(p.w);
        as[4] = f2tf(q.x); as[5] = f2tf(q.y); as[6] = f2tf(q.z); as[7] = f2tf(q.w);
#pragma unroll
        for (int r2 = 0; r2 < 2; r2++) {
            int k0 = kb + lwk + r2 * 8;
            int wsrc = PERM ? ((k0 & 255) * 3 + (k0 >> 8)) : k0;
            const float* wr = W + (size_t)wsrc * 256;
            unsigned* ws = &Ws[lwk + r2*8][0];
#pragma unroll
            for (int q4 = 0; q4 < 4; q4++) {
                float4 w = *(const float4*)(wr + lwc + q4 * 64);
                ws[lwc + q4*64 + 0] = f2tf(w.x); ws[lwc + q4*64 + 1] = f2tf(w.y);
                ws[lwc + q4*64 + 2] = f2tf(w.z); ws[lwc + q4*64 + 3] = f2tf(w.w);
            }
        }
        __syncthreads();
#pragma unroll
        for (int kk = 0; kk < 2; kk++) {
            unsigned af[4];
            af[0] = As[mrow + g    ][kk*8 + tig];
            af[1] = As[mrow + g + 8][kk*8 + tig];
            af[2] = As[mrow + g    ][kk*8 + tig + 4];
            af[3] = As[mrow + g + 8][kk*8 + tig + 4];
#pragma unroll
            for (int ni = 0; ni < 32; ni++) {
                unsigned b0 = Ws[kk*8 + tig    ][ni*8 + g];
                unsigned b1 = Ws[kk*8 + tig + 4][ni*8 + g];
                mma16n8k8(acc[ni], af, b0, b1);
            }
        }
        __syncthreads();
    }

    // epilogue: add bias, per-row LN stats (rows rA=.. and rB=..+8)
    float sumA = 0.f, sqA = 0.f, sumB = 0.f, sqB = 0.f;
#pragma unroll
    for (int ni = 0; ni < 32; ni++) {
        float2 b = *(const float2*)(bias + ni*8 + tig*2);
        acc[ni][0] += b.x; acc[ni][1] += b.y;
        acc[ni][2] += b.x; acc[ni][3] += b.y;
        sumA += acc[ni][0] + acc[ni][1];
        sqA  += acc[ni][0]*acc[ni][0] + acc[ni][1]*acc[ni][1];
        sumB += acc[ni][2] + acc[ni][3];
        sqB  += acc[ni][2]*acc[ni][2] + acc[ni][3]*acc[ni][3];
    }
    // 4 lanes (tig=0..3) of the same g cover the full 256-col row
#pragma unroll
    for (int m = 1; m <= 2; m <<= 1) {
        sumA += __shfl_xor_sync(0xffffffffu, sumA, m);
        sqA  += __shfl_xor_sync(0xffffffffu, sqA,  m);
        sumB += __shfl_xor_sync(0xffffffffu, sumB, m);
        sqB  += __shfl_xor_sync(0xffffffffu, sqB,  m);
    }
    const float meanA = sumA * (1.f/256.f);
    const float rstdA = rsqrtf(fmaxf(sqA * (1.f/256.f) - meanA*meanA, 0.f) + 1e-5f);
    const float meanB = sumB * (1.f/256.f);
    const float rstdB = rsqrtf(fmaxf(sqB * (1.f/256.f) - meanB*meanB, 0.f) + 1e-5f);

    const size_t rA = row0 + mrow + g;
    const size_t rB = rA + 8;
#pragma unroll
    for (int ni = 0; ni < 32; ni++) {
        int col = ni*8 + tig*2;
        size_t oA = rA * 256 + col;
        size_t oB = rB * 256 + col;
        float lnA0 = (acc[ni][0] - meanA) * rstdA;
        float lnA1 = (acc[ni][1] - meanA) * rstdA;
        float lnB0 = (acc[ni][2] - meanB) * rstdB;
        float lnB1 = (acc[ni][3] - meanB) * rstdB;
        float2 o1, o2;
        if (MODE == 0) {
            o1 = make_float2(lnA0, lnA1);
            o2 = make_float2(lnB0, lnB1);
        } else {
            float2 r1a = *(const float2*)(R1 + oA);
            float2 r1b = *(const float2*)(R1 + oB);
            float r2ax = 0.f, r2ay = 0.f, r2bx = 0.f, r2by = 0.f;
            if (MODE == 2) {
                float2 r2a = *(const float2*)(R2 + oA);
                float2 r2b = *(const float2*)(R2 + oB);
                r2ax = r2a.x; r2ay = r2a.y; r2bx = r2b.x; r2by = r2b.y;
            }
            o1 = make_float2(gelu_f(r1a.x + r2ax + lnA0), gelu_f(r1a.y + r2ay + lnA1));
            o2 = make_float2(gelu_f(r1b.x + r2bx + lnB0), gelu_f(r1b.y + r2by + lnB1));
        }
        *(float2*)(Out + oA) = o1;
        *(float2*)(Out + oB) = o2;
    }
}

// ---------------------------------------------------------------------------
// K2: spatial attention scores (fp32 SIMT, unchanged).
// ---------------------------------------------------------------------------
__global__ void __launch_bounds__(640) att_spatial_kernel(
    const float* __restrict__ Q, const float* __restrict__ K,
    const float* __restrict__ att0, float* __restrict__ ATTS)
{
    __shared__ __align__(16) float qt[25][68];
    __shared__ __align__(16) float kt[25][68];
    __shared__ float sa[25][26];
    const int tid = threadIdx.x;
    const int ns  = blockIdx.x;
    const int s   = ns % 3;
    const size_t base = (size_t)ns * (VV * TT * ICC);
    const int v = tid / 25, u = tid % 25;
    float acc = 0.f;

    for (int t = 0; t < 32; t++) {
        for (int idx = tid; idx < 3200; idx += 640) {
            int isk = (idx >= 1600);
            int i2 = idx - isk * 1600;
            int vv = i2 >> 6, cc = i2 & 63;
            float val = (isk ? K : Q)[base + vv * 2048 + t * 64 + cc];
            if (isk) kt[vv][cc] = val; else qt[vv][cc] = val;
        }
        __syncthreads();
        if (tid < 625) {
#pragma unroll
            for (int c4 = 0; c4 < 16; c4++) {
                float4 q4 = *(const float4*)&qt[v][c4 * 4];
                float4 k4 = *(const float4*)&kt[u][c4 * 4];
                acc += q4.x * k4.x + q4.y * k4.y + q4.z * k4.z + q4.w * k4.w;
            }
        }
        __syncthreads();
    }
    if (tid < 625) sa[v][u] = acc;
    __syncthreads();
    if (tid < 625) {
        float sum = 0.f;
#pragma unroll
        for (int uu = 0; uu < 25; uu++) sum += sa[v][uu];
        ATTS[ns * 625 + v * 25 + u] = acc / sum + att0[s * 625 + v * 25 + u];
    }
}

// ---------------------------------------------------------------------------
// K3: y = einsum('nsvu,ntuc->ntvcs', att, x) -> Y768 (col s*256+c).
// ---------------------------------------------------------------------------
__global__ void __launch_bounds__(256) y_spatial_kernel(
    const float* __restrict__ ATTS, const float* __restrict__ X,
    float* __restrict__ Y768)
{
    __shared__ __align__(16) float at[3][25][28];
    const int tid = threadIdx.x;
    const int nt  = blockIdx.x;
    const int n   = nt >> 5;
    for (int idx = tid; idx < 3 * 25 * 28; idx += 256) ((float*)at)[idx] = 0.f;
    __syncthreads();
    const float* asrc = ATTS + n * (3 * 625);
    for (int idx = tid; idx < 1875; idx += 256) {
        int s = idx / 625, rr = idx % 625;
        at[s][rr / 25][rr % 25] = asrc[idx];
    }
    float xreg[28];
    xreg[25] = xreg[26] = xreg[27] = 0.f;
    const int c = tid;
    const float* xb = X + (size_t)nt * (VV * CC) + c;
#pragma unroll
    for (int u = 0; u < 25; u++) xreg[u] = xb[u * 256];
    __syncthreads();

    for (int v = 0; v < 25; v++) {
        size_t ro = ((size_t)(nt * VV + v)) * 768 + c;
#pragma unroll
        for (int s = 0; s < 3; s++) {
            const float4* a4 = (const float4*)&at[s][v][0];
            float acc = 0.f;
#pragma unroll
            for (int u4 = 0; u4 < 7; u4++) {
                float4 a = a4[u4];
                acc += a.x * xreg[u4 * 4] + a.y * xreg[u4 * 4 + 1]
                     + a.z * xreg[u4 * 4 + 2] + a.w * xreg[u4 * 4 + 3];
            }
            Y768[ro + s * 256] = acc;
        }
    }
}

// ---------------------------------------------------------------------------
// K5: temporal attention (one direction), fp32 SIMT.
// ---------------------------------------------------------------------------
__global__ void __launch_bounds__(64) att_temporal_kernel(
    const float* __restrict__ Q, const float* __restrict__ K,
    float* __restrict__ ATT, int fwd)
{
    __shared__ __align__(16) float qt[32][68];
    __shared__ __align__(16) float kt[32][68];
    const int tid = threadIdx.x;
    const int ns  = blockIdx.x;
    const size_t base = (size_t)ns * (TT * VV * ICC);
    const int ti = tid >> 3, ki = tid & 7;
    float acc[4][4];
#pragma unroll
    for (int i = 0; i < 4; i++)
#pragma unroll
        for (int j = 0; j < 4; j++) acc[i][j] = 0.f;

    const int ltt = tid >> 1;
    const int lcc = (tid & 1) * 32;
    for (int v = 0; v < 25; v++) {
        const float* qsrc = Q + base + ltt * 1600 + v * 64 + lcc;
        const float* ksrc = K + base + ltt * 1600 + v * 64 + lcc;
#pragma unroll
        for (int q8 = 0; q8 < 8; q8++) {
            *(float4*)&qt[ltt][lcc + q8 * 4] = *(const float4*)(qsrc + q8 * 4);
            *(float4*)&kt[ltt][lcc + q8 * 4] = *(const float4*)(ksrc + q8 * 4);
        }
        __syncthreads();
#pragma unroll
        for (int c4 = 0; c4 < 16; c4++) {
            float4 q4[4], k4[4];
#pragma unroll
            for (int i = 0; i < 4; i++) q4[i] = *(const float4*)&qt[ti * 4 + i][c4 * 4];
#pragma unroll
            for (int j = 0; j < 4; j++) k4[j] = *(const float4*)&kt[ki * 4 + j][c4 * 4];
#pragma unroll
            for (int i = 0; i < 4; i++)
#pragma unroll
                for (int j = 0; j < 4; j++)
                    acc[i][j] += q4[i].x * k4[j].x + q4[i].y * k4[j].y
                               + q4[i].z * k4[j].z + q4[i].w * k4[j].w;
        }
        __syncthreads();
    }

#pragma unroll
    for (int i = 0; i < 4; i++) {
        int t = ti * 4 + i;
        float row[4];
        float rsum = 0.f;
#pragma unroll
        for (int j = 0; j < 4; j++) {
            int k = ki * 4 + j;
            bool valid = fwd ? (k <= t) : (k >= t);
            row[j] = valid ? acc[i][j] : 0.f;
            rsum += row[j];
        }
        rsum += __shfl_xor_sync(0xffffffffu, rsum, 1);
        rsum += __shfl_xor_sync(0xffffffffu, rsum, 2);
        rsum += __shfl_xor_sync(0xffffffffu, rsum, 4);
        float inv = 1.f / rsum;
#pragma unroll
        for (int j = 0; j < 4; j++)
            ATT[ns * 1024 + t * 32 + ki * 4 + j] = row[j] * inv;
    }
}

// ---------------------------------------------------------------------------
// K6: z = einsum('nstk,nkvc->ntvcs', a, y) for both directions.
// ---------------------------------------------------------------------------
__global__ void __launch_bounds__(256) z_temporal_kernel(
    const float* __restrict__ AF, const float* __restrict__ AB,
    const float* __restrict__ Y, float* __restrict__ ZF, float* __restrict__ ZB)
{
    __shared__ __align__(16) float af[3][32][32];
    __shared__ __align__(16) float ab[3][32][32];
    const int tid = threadIdx.x;
    const int blk = blockIdx.x;
    const int n = blk / 25, v = blk % 25;
    const float* afs = AF + n * 3072;
    const float* abz = AB + n * 3072;
    for (int idx = tid; idx < 3072; idx += 256) {
        ((float*)af)[idx] = afs[idx];
        ((float*)ab)[idx] = abz[idx];
    }
    float yreg[32];
    const int c = tid;
#pragma unroll
    for (int k = 0; k < 32; k++)
        yreg[k] = Y[((size_t)((n * 32 + k) * 25 + v)) * 256 + c];
    __syncthreads();

    for (int t = 0; t < 32; t++) {
        size_t ro = ((size_t)((n * 32 + t) * 25 + v)) * 768;
#pragma unroll
        for (int s = 0; s < 3; s++) {
            const float4* a4 = (const float4*)&af[s][t][0];
            const float4* b4 = (const float4*)&ab[s][t][0];
            float sf = 0.f, sb = 0.f;
#pragma unroll
            for (int k4 = 0; k4 < 8; k4++) {
                float4 a = a4[k4], b = b4[k4];
                sf += a.x * yreg[k4 * 4] + a.y * yreg[k4 * 4 + 1]
                    + a.z * yreg[k4 * 4 + 2] + a.w * yreg[k4 * 4 + 3];
                sb += b.x * yreg[k4 * 4] + b.y * yreg[k4 * 4 + 1]
                    + b.z * yreg[k4 * 4 + 2] + b.w * yreg[k4 * 4 + 3];
            }
            ZF[ro + s * 256 + c] = sf;
            ZB[ro + s * 256 + c] = sb;
        }
    }
}

// ---------------------------------------------------------------------------
extern "C" void kernel_launch(void* const* d_in, const int* in_sizes, int n_in,
                              void* d_out, int out_size)
{
    (void)in_sizes; (void)n_in; (void)out_size;
    const float* x        = (const float*)d_in[0];
    const float* w_in_s   = (const float*)d_in[1];
    const float* b_in_s   = (const float*)d_in[2];
    const float* att0     = (const float*)d_in[3];
    const float* w_out_s  = (const float*)d_in[4];
    const float* b_out_s  = (const float*)d_in[5];
    const float* w_ff_s   = (const float*)d_in[6];
    const float* b_ff_s   = (const float*)d_in[7];
    const float* w_in_tf  = (const float*)d_in[8];
    const float* b_in_tf  = (const float*)d_in[9];
    const float* w_in_tb  = (const float*)d_in[10];
    const float* b_in_tb  = (const float*)d_in[11];
    const float* w_out_tf = (const float*)d_in[12];
    const float* b_out_tf = (const float*)d_in[13];
    const float* w_out_tb = (const float*)d_in[14];
    const float* b_out_tb = (const float*)d_in[15];
    const float* w_ff_t   = (const float*)d_in[16];
    const float* b_ff_t   = (const float*)d_in[17];
    float* out = (float*)d_out;

    float *QA, *KA, *ATTS, *ATTF, *ATTB, *P768A, *P768B, *Y, *ZFln, *Z;
    cudaGetSymbolAddress((void**)&QA,    g_QA);
    cudaGetSymbolAddress((void**)&KA,    g_KA);
    cudaGetSymbolAddress((void**)&ATTS,  g_ATTS);
    cudaGetSymbolAddress((void**)&ATTF,  g_ATTF);
    cudaGetSymbolAddress((void**)&ATTB,  g_ATTB);
    cudaGetSymbolAddress((void**)&P768A, g_P768A);
    cudaGetSymbolAddress((void**)&P768B, g_P768B);
    cudaGetSymbolAddress((void**)&Y,     g_Y);
    cudaGetSymbolAddress((void**)&ZFln,  g_ZFln);
    cudaGetSymbolAddress((void**)&Z,     g_Z);

    const int nblkB = BROWS / 64;            // 1600
    dim3 gA(nblkB, 3);

    // ---- spatial block ----
    gemm_act_tc<0><<<gA, 128>>>(x, w_in_s, b_in_s, QA, KA);
    att_spatial_kernel<<<NN * SS, 640>>>(QA, KA, att0, ATTS);
    y_spatial_kernel<<<NN * TT, 256>>>(ATTS, x, P768A);                    // Y768
    gemm_ln_tc<768, 1, true ><<<nblkB, 128>>>(P768A, w_out_s, b_out_s, x, nullptr, Y);
    gemm_ln_tc<256, 1, false><<<nblkB, 128>>>(Y,     w_ff_s,  b_ff_s,  x, nullptr, Y);

    // ---- temporal block (Q/K buffers reused fwd then bwd) ----
    gemm_act_tc<1><<<gA, 128>>>(Y, w_in_tf, b_in_tf, QA, KA);
    att_temporal_kernel<<<NN * SS, 64>>>(QA, KA, ATTF, 1);
    gemm_act_tc<1><<<gA, 128>>>(Y, w_in_tb, b_in_tb, QA, KA);
    att_temporal_kernel<<<NN * SS, 64>>>(QA, KA, ATTB, 0);
    z_temporal_kernel<<<NN * VV, 256>>>(ATTF, ATTB, Y, P768A, P768B);      // Z768F, Z768B
    gemm_ln_tc<768, 0, true ><<<nblkB, 128>>>(P768A, w_out_tf, b_out_tf, nullptr, nullptr, ZFln);
    gemm_ln_tc<768, 2, true ><<<nblkB, 128>>>(P768B, w_out_tb, b_out_tb, Y, ZFln, Z);
    gemm_ln_tc<256, 1, false><<<nblkB, 128>>>(Z,     w_ff_t,   b_ff_t,  Y, nullptr, out);
}

// round 7
// speedup vs baseline: 3.1656x; 1.2012x over previous
#include <cuda_runtime.h>
#include <cuda_bf16.h>
#include <math.h>

// GPTNet: N=128, T=32, V=25, C=256, IC=64, S=3.  B = N*T*V = 102400 rows.
// R7 (= R6 resubmit after infra flake): tf32 GEMMs with 8 warps/block,
// warp tile m32xn64 (1.5 LDS/HMMA), 2 blocks/SM.
// 13 launches, graph-capturable, allocation-free.

#define NN 128
#define TT 32
#define VV 25
#define CC 256
#define ICC 64
#define SS 3
#define BROWS (NN*TT*VV)

__device__ float g_QA  [NN*SS*VV*TT*ICC];
__device__ float g_KA  [NN*SS*VV*TT*ICC];
__device__ float g_ATTS[NN*SS*VV*VV];
__device__ float g_ATTF[NN*SS*TT*TT];
__device__ float g_ATTB[NN*SS*TT*TT];
__device__ float g_P768A[(size_t)BROWS*768];     // Y768, later Z768F
__device__ float g_P768B[(size_t)BROWS*768];     // Z768B
__device__ float g_Y    [(size_t)BROWS*256];
__device__ float g_ZFln [(size_t)BROWS*256];
__device__ float g_Z    [(size_t)BROWS*256];

__device__ __forceinline__ float gelu_f(float x) {
    return 0.5f * x * (1.0f + erff(x * 0.70710678118654752f));
}

__device__ __forceinline__ unsigned f2tf(float v) {
    unsigned r;
    asm("cvt.rna.tf32.f32 %0, %1;" : "=r"(r) : "f"(v));
    return r;
}

// d += a(16x8,row) * b(8x8,col), tf32 inputs, fp32 accum
__device__ __forceinline__ void mma16n8k8(float* d, const unsigned* a,
                                          unsigned b0, unsigned b1) {
    asm volatile(
        "mma.sync.aligned.m16n8k8.row.col.f32.tf32.tf32.f32 "
        "{%0,%1,%2,%3}, {%4,%5,%6,%7}, {%8,%9}, {%0,%1,%2,%3};\n"
        : "+f"(d[0]), "+f"(d[1]), "+f"(d[2]), "+f"(d[3])
        : "r"(a[0]), "r"(a[1]), "r"(a[2]), "r"(a[3]), "r"(b0), "r"(b1));
}

// ---------------------------------------------------------------------------
// K1 (tensor): in-projection  out = elu(A[Bx256] @ W[256x384] + b) + 1, scatter.
// BM=128, BN=128 (grid.y=3), 256 thr (8 warps), warp grid 4m x 2n, tile m32xn64.
// ---------------------------------------------------------------------------
template<int MODE>
__global__ void __launch_bounds__(256, 2) gemm_act_tc(
    const float* __restrict__ A, const float* __restrict__ W,
    const float* __restrict__ bias, float* __restrict__ Qb, float* __restrict__ Kb)
{
    __shared__ __align__(16) unsigned As[128][20];
    __shared__ __align__(16) unsigned Ws[16][136];   // 136 % 32 == 8
    const int tid  = threadIdx.x;
    const int wid  = tid >> 5, lane = tid & 31;
    const int g    = lane >> 2, tig = lane & 3;
    const int mwarp = wid >> 1, nwarp = wid & 1;
    const int row0 = blockIdx.x * 128;
    const int col0 = blockIdx.y * 128;

    float acc[2][8][4];
#pragma unroll
    for (int tm = 0; tm < 2; tm++)
#pragma unroll
        for (int ni = 0; ni < 8; ni++)
#pragma unroll
            for (int j = 0; j < 4; j++) acc[tm][ni][j] = 0.f;

    const int ar = tid >> 1;                // 0..127
    const int ak = (tid & 1) * 8;           // 0 or 8
    const float* Arow = A + (size_t)(row0 + ar) * 256 + ak;
    const int wrk = tid >> 4;               // 0..15
    const int wrc = (tid & 15) * 8;         // 0..120

    for (int kb = 0; kb < 256; kb += 16) {
        float4 p = *(const float4*)(Arow + kb);
        float4 q = *(const float4*)(Arow + kb + 4);
        unsigned* as = &As[ar][ak];
        as[0] = f2tf(p.x); as[1] = f2tf(p.y); as[2] = f2tf(p.z); as[3] = f2tf(p.w);
        as[4] = f2tf(q.x); as[5] = f2tf(q.y); as[6] = f2tf(q.z); as[7] = f2tf(q.w);
        const float* wr = W + (size_t)(kb + wrk) * 384 + col0 + wrc;
        unsigned* ws = &Ws[wrk][wrc];
#pragma unroll
        for (int j4 = 0; j4 < 2; j4++) {
            float4 w = *(const float4*)(wr + j4 * 4);
            ws[j4*4+0] = f2tf(w.x); ws[j4*4+1] = f2tf(w.y);
            ws[j4*4+2] = f2tf(w.z); ws[j4*4+3] = f2tf(w.w);
        }
        __syncthreads();
#pragma unroll
        for (int kk = 0; kk < 2; kk++) {
            unsigned af[2][4];
#pragma unroll
            for (int tm = 0; tm < 2; tm++) {
                int rb = mwarp * 32 + tm * 16;
                af[tm][0] = As[rb + g    ][kk*8 + tig];
                af[tm][1] = As[rb + g + 8][kk*8 + tig];
                af[tm][2] = As[rb + g    ][kk*8 + tig + 4];
                af[tm][3] = As[rb + g + 8][kk*8 + tig + 4];
            }
#pragma unroll
            for (int ni = 0; ni < 8; ni++) {
                unsigned b0 = Ws[kk*8 + tig    ][nwarp*64 + ni*8 + g];
                unsigned b1 = Ws[kk*8 + tig + 4][nwarp*64 + ni*8 + g];
                mma16n8k8(acc[0][ni], af[0], b0, b1);
                mma16n8k8(acc[1][ni], af[1], b0, b1);
            }
        }
        __syncthreads();
    }

    auto scatter = [&](int rn, int rt, int rv, int jg, float val) {
        val = (val > 0.f) ? (val + 1.f) : expf(val);     // elu(x)+1
        int c = jg / 6, ss = jg % 6;
        int s = (ss < 3) ? ss : ss - 3;
        float* dst = (ss < 3) ? Qb : Kb;
        size_t off;
        if (MODE == 0)
            off = ((size_t)(rn * 3 + s) * VV + rv) * (TT * ICC) + rt * ICC + c;
        else
            off = ((size_t)(rn * 3 + s) * TT + rt) * (VV * ICC) + rv * ICC + c;
        dst[off] = val;
    };

#pragma unroll
    for (int tm = 0; tm < 2; tm++) {
        const int rA = row0 + mwarp*32 + tm*16 + g;
        const int rB = rA + 8;
        const int nA = rA/(TT*VV), remA = rA%(TT*VV), tA = remA/VV, vA = remA%VV;
        const int nB = rB/(TT*VV), remB = rB%(TT*VV), tB = remB/VV, vB = remB%VV;
#pragma unroll
        for (int ni = 0; ni < 8; ni++) {
            int jg0 = col0 + nwarp*64 + ni*8 + tig*2;
            float2 b = *(const float2*)(bias + jg0);
            scatter(nA, tA, vA, jg0,     acc[tm][ni][0] + b.x);
            scatter(nA, tA, vA, jg0 + 1, acc[tm][ni][1] + b.y);
            scatter(nB, tB, vB, jg0,     acc[tm][ni][2] + b.x);
            scatter(nB, tB, vB, jg0 + 1, acc[tm][ni][3] + b.y);
        }
    }
}

// ---------------------------------------------------------------------------
// K4 (tensor): GEMM (B x KDIM) @ (KDIM x 256) + bias, fused LN epilogue.
// MODE 0: LN ; 1: gelu(R1+LN) ; 2: gelu(R1+R2+LN).  PERM: W row = c*3+s.
// BM=64, BN=256, 256 thr (8 warps), warp grid 2m x 4n, tile m32 x n64.
// LN: cross-warp reduction over the 4 n-warps via smem.
// ---------------------------------------------------------------------------
template<int KDIM, int MODE, bool PERM>
__global__ void __launch_bounds__(256, 2) gemm_ln_tc(
    const float* __restrict__ A, const float* __restrict__ W,
    const float* __restrict__ bias,
    const float* __restrict__ R1, const float* __restrict__ R2,
    float* __restrict__ Out)
{
    __shared__ __align__(16) unsigned As[64][20];
    __shared__ __align__(16) unsigned Ws[16][264];   // 264 % 32 == 8
    __shared__ float red_s[64][4];
    __shared__ float red_q[64][4];
    const int tid  = threadIdx.x;
    const int wid  = tid >> 5, lane = tid & 31;
    const int g    = lane >> 2, tig = lane & 3;
    const int mwarp = wid >> 2, nwarp = wid & 3;
    const size_t row0 = (size_t)blockIdx.x * 64;

    float acc[2][8][4];
#pragma unroll
    for (int tm = 0; tm < 2; tm++)
#pragma unroll
        for (int ni = 0; ni < 8; ni++)
#pragma unroll
            for (int j = 0; j < 4; j++) acc[tm][ni][j] = 0.f;

    const int ar = tid >> 2;                // 0..63
    const int ak = (tid & 3) * 4;           // 0,4,8,12
    const float* Arow = A + (row0 + ar) * KDIM + ak;
    const int lwk = tid >> 4;               // 0..15
    const int lwc = (tid & 15) * 4;         // 0..60

    for (int kb = 0; kb < KDIM; kb += 16) {
        float4 p = *(const float4*)(Arow + kb);
        unsigned* as = &As[ar][ak];
        as[0] = f2tf(p.x); as[1] = f2tf(p.y); as[2] = f2tf(p.z); as[3] = f2tf(p.w);
        int k0 = kb + lwk;
        int wsrc = PERM ? ((k0 & 255) * 3 + (k0 >> 8)) : k0;
        const float* wr = W + (size_t)wsrc * 256;
        unsigned* ws = &Ws[lwk][0];
#pragma unroll
        for (int q4 = 0; q4 < 4; q4++) {
            float4 w = *(const float4*)(wr + lwc + q4 * 64);
            ws[lwc + q4*64 + 0] = f2tf(w.x); ws[lwc + q4*64 + 1] = f2tf(w.y);
            ws[lwc + q4*64 + 2] = f2tf(w.z); ws[lwc + q4*64 + 3] = f2tf(w.w);
        }
        __syncthreads();
#pragma unroll
        for (int kk = 0; kk < 2; kk++) {
            unsigned af[2][4];
#pragma unroll
            for (int tm = 0; tm < 2; tm++) {
                int rb = mwarp * 32 + tm * 16;
                af[tm][0] = As[rb + g    ][kk*8 + tig];
                af[tm][1] = As[rb + g + 8][kk*8 + tig];
                af[tm][2] = As[rb + g    ][kk*8 + tig + 4];
                af[tm][3] = As[rb + g + 8][kk*8 + tig + 4];
            }
#pragma unroll
            for (int ni = 0; ni < 8; ni++) {
                unsigned b0 = Ws[kk*8 + tig    ][nwarp*64 + ni*8 + g];
                unsigned b1 = Ws[kk*8 + tig + 4][nwarp*64 + ni*8 + g];
                mma16n8k8(acc[0][ni], af[0], b0, b1);
                mma16n8k8(acc[1][ni], af[1], b0, b1);
            }
        }
        __syncthreads();
    }

    // ---- epilogue: bias, cross-warp LN, residual/gelu ----
    float psum[2][2] = {{0.f,0.f},{0.f,0.f}};
    float psq [2][2] = {{0.f,0.f},{0.f,0.f}};
#pragma unroll
    for (int tm = 0; tm < 2; tm++)
#pragma unroll
        for (int ni = 0; ni < 8; ni++) {
            float2 b = *(const float2*)(bias + nwarp*64 + ni*8 + tig*2);
            acc[tm][ni][0] += b.x; acc[tm][ni][1] += b.y;
            acc[tm][ni][2] += b.x; acc[tm][ni][3] += b.y;
            psum[tm][0] += acc[tm][ni][0] + acc[tm][ni][1];
            psq [tm][0] += acc[tm][ni][0]*acc[tm][ni][0] + acc[tm][ni][1]*acc[tm][ni][1];
            psum[tm][1] += acc[tm][ni][2] + acc[tm][ni][3];
            psq [tm][1] += acc[tm][ni][2]*acc[tm][ni][2] + acc[tm][ni][3]*acc[tm][ni][3];
        }
#pragma unroll
    for (int m = 1; m <= 2; m <<= 1)
#pragma unroll
        for (int tm = 0; tm < 2; tm++)
#pragma unroll
            for (int h = 0; h < 2; h++) {
                psum[tm][h] += __shfl_xor_sync(0xffffffffu, psum[tm][h], m);
                psq [tm][h] += __shfl_xor_sync(0xffffffffu, psq [tm][h], m);
            }
    if (tig == 0) {
#pragma unroll
        for (int tm = 0; tm < 2; tm++)
#pragma unroll
            for (int h = 0; h < 2; h++) {
                int lr = mwarp*32 + tm*16 + g + h*8;
                red_s[lr][nwarp] = psum[tm][h];
                red_q[lr][nwarp] = psq [tm][h];
            }
    }
    __syncthreads();

    float mean_[2][2], rstd_[2][2];
#pragma unroll
    for (int tm = 0; tm < 2; tm++)
#pragma unroll
        for (int h = 0; h < 2; h++) {
            int lr = mwarp*32 + tm*16 + g + h*8;
            float s = red_s[lr][0] + red_s[lr][1] + red_s[lr][2] + red_s[lr][3];
            float q = red_q[lr][0] + red_q[lr][1] + red_q[lr][2] + red_q[lr][3];
            float mn = s * (1.f/256.f);
            mean_[tm][h] = mn;
            rstd_[tm][h] = rsqrtf(fmaxf(q * (1.f/256.f) - mn*mn, 0.f) + 1e-5f);
        }

#pragma unroll
    for (int tm = 0; tm < 2; tm++) {
        const size_t rA = row0 + mwarp*32 + tm*16 + g;
        const size_t rB = rA + 8;
#pragma unroll
        for (int ni = 0; ni < 8; ni++) {
            int col = nwarp*64 + ni*8 + tig*2;
            size_t oA = rA * 256 + col;
            size_t oB = rB * 256 + col;
            float lnA0 = (acc[tm][ni][0] - mean_[tm][0]) * rstd_[tm][0];
            float lnA1 = (acc[tm][ni][1] - mean_[tm][0]) * rstd_[tm][0];
            float lnB0 = (acc[tm][ni][2] - mean_[tm][1]) * rstd_[tm][1];
            float lnB1 = (acc[tm][ni][3] - mean_[tm][1]) * rstd_[tm][1];
            float2 o1, o2;
            if (MODE == 0) {
                o1 = make_float2(lnA0, lnA1);
                o2 = make_float2(lnB0, lnB1);
            } else {
                float2 r1a = *(const float2*)(R1 + oA);
                float2 r1b = *(const float2*)(R1 + oB);
                float r2ax = 0.f, r2ay = 0.f, r2bx = 0.f, r2by = 0.f;
                if (MODE == 2) {
                    float2 r2a = *(const float2*)(R2 + oA);
                    float2 r2b = *(const float2*)(R2 + oB);
                    r2ax = r2a.x; r2ay = r2a.y; r2bx = r2b.x; r2by = r2b.y;
                }
                o1 = make_float2(gelu_f(r1a.x + r2ax + lnA0), gelu_f(r1a.y + r2ay + lnA1));
                o2 = make_float2(gelu_f(r1b.x + r2bx + lnB0), gelu_f(r1b.y + r2by + lnB1));
            }
            *(float2*)(Out + oA) = o1;
            *(float2*)(Out + oB) = o2;
        }
    }
}

// ---------------------------------------------------------------------------
// K2: spatial attention scores (fp32 SIMT).
// ---------------------------------------------------------------------------
__global__ void __launch_bounds__(640) att_spatial_kernel(
    const float* __restrict__ Q, const float* __restrict__ K,
    const float* __restrict__ att0, float* __restrict__ ATTS)
{
    __shared__ __align__(16) float qt[25][68];
    __shared__ __align__(16) float kt[25][68];
    __shared__ float sa[25][26];
    const int tid = threadIdx.x;
    const int ns  = blockIdx.x;
    const int s   = ns % 3;
    const size_t base = (size_t)ns * (VV * TT * ICC);
    const int v = tid / 25, u = tid % 25;
    float acc = 0.f;

    for (int t = 0; t < 32; t++) {
        for (int idx = tid; idx < 3200; idx += 640) {
            int isk = (idx >= 1600);
            int i2 = idx - isk * 1600;
            int vv = i2 >> 6, cc = i2 & 63;
            float val = (isk ? K : Q)[base + vv * 2048 + t * 64 + cc];
            if (isk) kt[vv][cc] = val; else qt[vv][cc] = val;
        }
        __syncthreads();
        if (tid < 625) {
#pragma unroll
            for (int c4 = 0; c4 < 16; c4++) {
                float4 q4 = *(const float4*)&qt[v][c4 * 4];
                float4 k4 = *(const float4*)&kt[u][c4 * 4];
                acc += q4.x * k4.x + q4.y * k4.y + q4.z * k4.z + q4.w * k4.w;
            }
        }
        __syncthreads();
    }
    if (tid < 625) sa[v][u] = acc;
    __syncthreads();
    if (tid < 625) {
        float sum = 0.f;
#pragma unroll
        for (int uu = 0; uu < 25; uu++) sum += sa[v][uu];
        ATTS[ns * 625 + v * 25 + u] = acc / sum + att0[s * 625 + v * 25 + u];
    }
}

// ---------------------------------------------------------------------------
// K3: y = einsum('nsvu,ntuc->ntvcs', att, x) -> Y768 (col s*256+c).
// ---------------------------------------------------------------------------
__global__ void __launch_bounds__(256) y_spatial_kernel(
    const float* __restrict__ ATTS, const float* __restrict__ X,
    float* __restrict__ Y768)
{
    __shared__ __align__(16) float at[3][25][28];
    const int tid = threadIdx.x;
    const int nt  = blockIdx.x;
    const int n   = nt >> 5;
    for (int idx = tid; idx < 3 * 25 * 28; idx += 256) ((float*)at)[idx] = 0.f;
    __syncthreads();
    const float* asrc = ATTS + n * (3 * 625);
    for (int idx = tid; idx < 1875; idx += 256) {
        int s = idx / 625, rr = idx % 625;
        at[s][rr / 25][rr % 25] = asrc[idx];
    }
    float xreg[28];
    xreg[25] = xreg[26] = xreg[27] = 0.f;
    const int c = tid;
    const float* xb = X + (size_t)nt * (VV * CC) + c;
#pragma unroll
    for (int u = 0; u < 25; u++) xreg[u] = xb[u * 256];
    __syncthreads();

    for (int v = 0; v < 25; v++) {
        size_t ro = ((size_t)(nt * VV + v)) * 768 + c;
#pragma unroll
        for (int s = 0; s < 3; s++) {
            const float4* a4 = (const float4*)&at[s][v][0];
            float acc = 0.f;
#pragma unroll
            for (int u4 = 0; u4 < 7; u4++) {
                float4 a = a4[u4];
                acc += a.x * xreg[u4 * 4] + a.y * xreg[u4 * 4 + 1]
                     + a.z * xreg[u4 * 4 + 2] + a.w * xreg[u4 * 4 + 3];
            }
            Y768[ro + s * 256] = acc;
        }
    }
}

// ---------------------------------------------------------------------------
// K5: temporal attention (one direction), fp32 SIMT.
// ---------------------------------------------------------------------------
__global__ void __launch_bounds__(64) att_temporal_kernel(
    const float* __restrict__ Q, const float* __restrict__ K,
    float* __restrict__ ATT, int fwd)
{
    __shared__ __align__(16) float qt[32][68];
    __shared__ __align__(16) float kt[32][68];
    const int tid = threadIdx.x;
    const int ns  = blockIdx.x;
    const size_t base = (size_t)ns * (TT * VV * ICC);
    const int ti = tid >> 3, ki = tid & 7;
    float acc[4][4];
#pragma unroll
    for (int i = 0; i < 4; i++)
#pragma unroll
        for (int j = 0; j < 4; j++) acc[i][j] = 0.f;

    const int ltt = tid >> 1;
    const int lcc = (tid & 1) * 32;
    for (int v = 0; v < 25; v++) {
        const float* qsrc = Q + base + ltt * 1600 + v * 64 + lcc;
        const float* ksrc = K + base + ltt * 1600 + v * 64 + lcc;
#pragma unroll
        for (int q8 = 0; q8 < 8; q8++) {
            *(float4*)&qt[ltt][lcc + q8 * 4] = *(const float4*)(qsrc + q8 * 4);
            *(float4*)&kt[ltt][lcc + q8 * 4] = *(const float4*)(ksrc + q8 * 4);
        }
        __syncthreads();
#pragma unroll
        for (int c4 = 0; c4 < 16; c4++) {
            float4 q4[4], k4[4];
#pragma unroll
            for (int i = 0; i < 4; i++) q4[i] = *(const float4*)&qt[ti * 4 + i][c4 * 4];
#pragma unroll
            for (int j = 0; j < 4; j++) k4[j] = *(const float4*)&kt[ki * 4 + j][c4 * 4];
#pragma unroll
            for (int i = 0; i < 4; i++)
#pragma unroll
                for (int j = 0; j < 4; j++)
                    acc[i][j] += q4[i].x * k4[j].x + q4[i].y * k4[j].y
                               + q4[i].z * k4[j].z + q4[i].w * k4[j].w;
        }
        __syncthreads();
    }

#pragma unroll
    for (int i = 0; i < 4; i++) {
        int t = ti * 4 + i;
        float row[4];
        float rsum = 0.f;
#pragma unroll
        for (int j = 0; j < 4; j++) {
            int k = ki * 4 + j;
            bool valid = fwd ? (k <= t) : (k >= t);
            row[j] = valid ? acc[i][j] : 0.f;
            rsum += row[j];
        }
        rsum += __shfl_xor_sync(0xffffffffu, rsum, 1);
        rsum += __shfl_xor_sync(0xffffffffu, rsum, 2);
        rsum += __shfl_xor_sync(0xffffffffu, rsum, 4);
        float inv = 1.f / rsum;
#pragma unroll
        for (int j = 0; j < 4; j++)
            ATT[ns * 1024 + t * 32 + ki * 4 + j] = row[j] * inv;
    }
}

// ---------------------------------------------------------------------------
// K6: z = einsum('nstk,nkvc->ntvcs', a, y) for both directions.
// ---------------------------------------------------------------------------
__global__ void __launch_bounds__(256) z_temporal_kernel(
    const float* __restrict__ AF, const float* __restrict__ AB,
    const float* __restrict__ Y, float* __restrict__ ZF, float* __restrict__ ZB)
{
    __shared__ __align__(16) float af[3][32][32];
    __shared__ __align__(16) float ab[3][32][32];
    const int tid = threadIdx.x;
    const int blk = blockIdx.x;
    const int n = blk / 25, v = blk % 25;
    const float* afs = AF + n * 3072;
    const float* abz = AB + n * 3072;
    for (int idx = tid; idx < 3072; idx += 256) {
        ((float*)af)[idx] = afs[idx];
        ((float*)ab)[idx] = abz[idx];
    }
    float yreg[32];
    const int c = tid;
#pragma unroll
    for (int k = 0; k < 32; k++)
        yreg[k] = Y[((size_t)((n * 32 + k) * 25 + v)) * 256 + c];
    __syncthreads();

    for (int t = 0; t < 32; t++) {
        size_t ro = ((size_t)((n * 32 + t) * 25 + v)) * 768;
#pragma unroll
        for (int s = 0; s < 3; s++) {
            const float4* a4 = (const float4*)&af[s][t][0];
            const float4* b4 = (const float4*)&ab[s][t][0];
            float sf = 0.f, sb = 0.f;
#pragma unroll
            for (int k4 = 0; k4 < 8; k4++) {
                float4 a = a4[k4], b = b4[k4];
                sf += a.x * yreg[k4 * 4] + a.y * yreg[k4 * 4 + 1]
                    + a.z * yreg[k4 * 4 + 2] + a.w * yreg[k4 * 4 + 3];
                sb += b.x * yreg[k4 * 4] + b.y * yreg[k4 * 4 + 1]
                    + b.z * yreg[k4 * 4 + 2] + b.w * yreg[k4 * 4 + 3];
            }
            ZF[ro + s * 256 + c] = sf;
            ZB[ro + s * 256 + c] = sb;
        }
    }
}

// ---------------------------------------------------------------------------
extern "C" void kernel_launch(void* const* d_in, const int* in_sizes, int n_in,
                              void* d_out, int out_size)
{
    (void)in_sizes; (void)n_in; (void)out_size;
    const float* x        = (const float*)d_in[0];
    const float* w_in_s   = (const float*)d_in[1];
    const float* b_in_s   = (const float*)d_in[2];
    const float* att0     = (const float*)d_in[3];
    const float* w_out_s  = (const float*)d_in[4];
    const float* b_out_s  = (const float*)d_in[5];
    const float* w_ff_s   = (const float*)d_in[6];
    const float* b_ff_s   = (const float*)d_in[7];
    const float* w_in_tf  = (const float*)d_in[8];
    const float* b_in_tf  = (const float*)d_in[9];
    const float* w_in_tb  = (const float*)d_in[10];
    const float* b_in_tb  = (const float*)d_in[11];
    const float* w_out_tf = (const float*)d_in[12];
    const float* b_out_tf = (const float*)d_in[13];
    const float* w_out_tb = (const float*)d_in[14];
    const float* b_out_tb = (const float*)d_in[15];
    const float* w_ff_t   = (const float*)d_in[16];
    const float* b_ff_t   = (const float*)d_in[17];
    float* out = (float*)d_out;

    float *QA, *KA, *ATTS, *ATTF, *ATTB, *P768A, *P768B, *Y, *ZFln, *Z;
    cudaGetSymbolAddress((void**)&QA,    g_QA);
    cudaGetSymbolAddress((void**)&KA,    g_KA);
    cudaGetSymbolAddress((void**)&ATTS,  g_ATTS);
    cudaGetSymbolAddress((void**)&ATTF,  g_ATTF);
    cudaGetSymbolAddress((void**)&ATTB,  g_ATTB);
    cudaGetSymbolAddress((void**)&P768A, g_P768A);
    cudaGetSymbolAddress((void**)&P768B, g_P768B);
    cudaGetSymbolAddress((void**)&Y,     g_Y);
    cudaGetSymbolAddress((void**)&ZFln,  g_ZFln);
    cudaGetSymbolAddress((void**)&Z,     g_Z);

    const int nblkLN = BROWS / 64;           // 1600
    dim3 gA(BROWS / 128, 3);                 // (800, 3)

    // ---- spatial block ----
    gemm_act_tc<0><<<gA, 256>>>(x, w_in_s, b_in_s, QA, KA);
    att_spatial_kernel<<<NN * SS, 640>>>(QA, KA, att0, ATTS);
    y_spatial_kernel<<<NN * TT, 256>>>(ATTS, x, P768A);                    // Y768
    gemm_ln_tc<768, 1, true ><<<nblkLN, 256>>>(P768A, w_out_s, b_out_s, x, nullptr, Y);
    gemm_ln_tc<256, 1, false><<<nblkLN, 256>>>(Y,     w_ff_s,  b_ff_s,  x, nullptr, Y);

    // ---- temporal block (Q/K buffers reused fwd then bwd) ----
    gemm_act_tc<1><<<gA, 256>>>(Y, w_in_tf, b_in_tf, QA, KA);
    att_temporal_kernel<<<NN * SS, 64>>>(QA, KA, ATTF, 1);
    gemm_act_tc<1><<<gA, 256>>>(Y, w_in_tb, b_in_tb, QA, KA);
    att_temporal_kernel<<<NN * SS, 64>>>(QA, KA, ATTB, 0);
    z_temporal_kernel<<<NN * VV, 256>>>(ATTF, ATTB, Y, P768A, P768B);      // Z768F, Z768B
    gemm_ln_tc<768, 0, true ><<<nblkLN, 256>>>(P768A, w_out_tf, b_out_tf, nullptr, nullptr, ZFln);
    gemm_ln_tc<768, 2, true ><<<nblkLN, 256>>>(P768B, w_out_tb, b_out_tb, Y, ZFln, Z);
    gemm_ln_tc<256, 1, false><<<nblkLN, 256>>>(Z,     w_ff_t,   b_ff_t,  Y, nullptr, out);
}

// round 8
// speedup vs baseline: 3.4922x; 1.1032x over previous
#include <cuda_runtime.h>
#include <cuda_bf16.h>
#include <math.h>

// GPTNet: N=128, T=32, V=25, C=256, IC=64, S=3.  B = N*T*V = 102400 rows.
// R8: tf32 weights pre-converted/pre-permuted once (prep kernel); GEMM
// mainloops register-prefetch pipelined. 14 launches, graph-capturable.

#define NN 128
#define TT 32
#define VV 25
#define CC 256
#define ICC 64
#define SS 3
#define BROWS (NN*TT*VV)

__device__ float g_QA  [NN*SS*VV*TT*ICC];
__device__ float g_KA  [NN*SS*VV*TT*ICC];
__device__ float g_ATTS[NN*SS*VV*VV];
__device__ float g_ATTF[NN*SS*TT*TT];
__device__ float g_ATTB[NN*SS*TT*TT];
__device__ float g_P768A[(size_t)BROWS*768];     // Y768, later Z768F
__device__ float g_P768B[(size_t)BROWS*768];     // Z768B
__device__ float g_Y    [(size_t)BROWS*256];
__device__ float g_ZFln [(size_t)BROWS*256];
__device__ float g_Z    [(size_t)BROWS*256];

// pre-converted tf32 weights (permuted where needed)
#define WT_IN_S   0
#define WT_IN_TF  (256*384)
#define WT_IN_TB  (2*256*384)
#define WT_OUT_S  (3*256*384)
#define WT_OUT_TF (WT_OUT_S + 768*256)
#define WT_OUT_TB (WT_OUT_S + 2*768*256)
#define WT_FF_S   (WT_OUT_S + 3*768*256)
#define WT_FF_T   (WT_FF_S + 256*256)
#define WT_TOTAL  (WT_FF_S + 2*256*256)
__device__ unsigned g_Wt[WT_TOTAL];

__device__ __forceinline__ float gelu_f(float x) {
    return 0.5f * x * (1.0f + erff(x * 0.70710678118654752f));
}

__device__ __forceinline__ unsigned f2tf(float v) {
    unsigned r;
    asm("cvt.rna.tf32.f32 %0, %1;" : "=r"(r) : "f"(v));
    return r;
}

// d += a(16x8,row) * b(8x8,col), tf32 inputs, fp32 accum
__device__ __forceinline__ void mma16n8k8(float* d, const unsigned* a,
                                          unsigned b0, unsigned b1) {
    asm volatile(
        "mma.sync.aligned.m16n8k8.row.col.f32.tf32.tf32.f32 "
        "{%0,%1,%2,%3}, {%4,%5,%6,%7}, {%8,%9}, {%0,%1,%2,%3};\n"
        : "+f"(d[0]), "+f"(d[1]), "+f"(d[2]), "+f"(d[3])
        : "r"(a[0]), "r"(a[1]), "r"(a[2]), "r"(a[3]), "r"(b0), "r"(b1));
}

// ---------------------------------------------------------------------------
// K0: weight prep — tf32 conversion (+ row permutation k -> (k&255)*3+(k>>8)
// for the 768-row out-projections). grid (96, 8), 256 thr.
// ---------------------------------------------------------------------------
__global__ void prep_weights(
    const float* __restrict__ w_in_s,  const float* __restrict__ w_in_tf,
    const float* __restrict__ w_in_tb, const float* __restrict__ w_out_s,
    const float* __restrict__ w_out_tf,const float* __restrict__ w_out_tb,
    const float* __restrict__ w_ff_s,  const float* __restrict__ w_ff_t,
    unsigned* __restrict__ Wt)
{
    const int m = blockIdx.y;
    const float* src; unsigned* dst; int n; bool perm;
    switch (m) {
        case 0: src = w_in_s;   dst = Wt + WT_IN_S;   n = 256*384; perm = false; break;
        case 1: src = w_in_tf;  dst = Wt + WT_IN_TF;  n = 256*384; perm = false; break;
        case 2: src = w_in_tb;  dst = Wt + WT_IN_TB;  n = 256*384; perm = false; break;
        case 3: src = w_out_s;  dst = Wt + WT_OUT_S;  n = 768*256; perm = true;  break;
        case 4: src = w_out_tf; dst = Wt + WT_OUT_TF; n = 768*256; perm = true;  break;
        case 5: src = w_out_tb; dst = Wt + WT_OUT_TB; n = 768*256; perm = true;  break;
        case 6: src = w_ff_s;   dst = Wt + WT_FF_S;   n = 256*256; perm = false; break;
        default:src = w_ff_t;   dst = Wt + WT_FF_T;   n = 256*256; perm = false; break;
    }
    for (int i = blockIdx.x * 256 + threadIdx.x; i < n; i += gridDim.x * 256) {
        int idx = i;
        if (perm) {
            int k = i >> 8, c = i & 255;
            idx = ((k & 255) * 3 + (k >> 8)) * 256 + c;
        }
        dst[i] = f2tf(src[idx]);
    }
}

// ---------------------------------------------------------------------------
// K1 (tensor): in-projection  out = elu(A[Bx256] @ W[256x384] + b) + 1, scatter.
// BM=128, BN=128 (grid.y=3), 256 thr, warp grid 4m x 2n, tile m32xn64.
// W pre-tf32; register-prefetch pipelined mainloop.
// ---------------------------------------------------------------------------
template<int MODE>
__global__ void __launch_bounds__(256, 2) gemm_act_tc(
    const float* __restrict__ A, const unsigned* __restrict__ W,
    const float* __restrict__ bias, float* __restrict__ Qb, float* __restrict__ Kb)
{
    __shared__ __align__(16) unsigned As[128][20];
    __shared__ __align__(16) unsigned Ws[16][136];   // 136 % 32 == 8
    const int tid  = threadIdx.x;
    const int wid  = tid >> 5, lane = tid & 31;
    const int g    = lane >> 2, tig = lane & 3;
    const int mwarp = wid >> 1, nwarp = wid & 1;
    const int row0 = blockIdx.x * 128;
    const int col0 = blockIdx.y * 128;

    float acc[2][8][4];
#pragma unroll
    for (int tm = 0; tm < 2; tm++)
#pragma unroll
        for (int ni = 0; ni < 8; ni++)
#pragma unroll
            for (int j = 0; j < 4; j++) acc[tm][ni][j] = 0.f;

    const int ar = tid >> 1;                // 0..127
    const int ak = (tid & 1) * 8;           // 0 or 8
    const float* Arow = A + (size_t)(row0 + ar) * 256 + ak;
    const int wrk = tid >> 4;               // 0..15
    const int wrc = (tid & 15) * 8;         // 0..120
    const unsigned* Wbase = W + (size_t)wrk * 384 + col0 + wrc;

    // prologue prefetch (kb = 0)
    float4 pA0 = *(const float4*)(Arow);
    float4 pA1 = *(const float4*)(Arow + 4);
    uint4  pW0 = *(const uint4*)(Wbase);
    uint4  pW1 = *(const uint4*)(Wbase + 4);

    for (int kb = 0; kb < 256; kb += 16) {
        unsigned* as = &As[ar][ak];
        as[0] = f2tf(pA0.x); as[1] = f2tf(pA0.y); as[2] = f2tf(pA0.z); as[3] = f2tf(pA0.w);
        as[4] = f2tf(pA1.x); as[5] = f2tf(pA1.y); as[6] = f2tf(pA1.z); as[7] = f2tf(pA1.w);
        *(uint4*)&Ws[wrk][wrc]     = pW0;
        *(uint4*)&Ws[wrk][wrc + 4] = pW1;
        __syncthreads();
        if (kb + 16 < 256) {
            pA0 = *(const float4*)(Arow + kb + 16);
            pA1 = *(const float4*)(Arow + kb + 20);
            pW0 = *(const uint4*)(Wbase + (size_t)(kb + 16) * 384);
            pW1 = *(const uint4*)(Wbase + (size_t)(kb + 16) * 384 + 4);
        }
#pragma unroll
        for (int kk = 0; kk < 2; kk++) {
            unsigned af[2][4];
#pragma unroll
            for (int tm = 0; tm < 2; tm++) {
                int rb = mwarp * 32 + tm * 16;
                af[tm][0] = As[rb + g    ][kk*8 + tig];
                af[tm][1] = As[rb + g + 8][kk*8 + tig];
                af[tm][2] = As[rb + g    ][kk*8 + tig + 4];
                af[tm][3] = As[rb + g + 8][kk*8 + tig + 4];
            }
#pragma unroll
            for (int ni = 0; ni < 8; ni++) {
                unsigned b0 = Ws[kk*8 + tig    ][nwarp*64 + ni*8 + g];
                unsigned b1 = Ws[kk*8 + tig + 4][nwarp*64 + ni*8 + g];
                mma16n8k8(acc[0][ni], af[0], b0, b1);
                mma16n8k8(acc[1][ni], af[1], b0, b1);
            }
        }
        __syncthreads();
    }

    auto scatter = [&](int rn, int rt, int rv, int jg, float val) {
        val = (val > 0.f) ? (val + 1.f) : expf(val);     // elu(x)+1
        int c = jg / 6, ss = jg % 6;
        int s = (ss < 3) ? ss : ss - 3;
        float* dst = (ss < 3) ? Qb : Kb;
        size_t off;
        if (MODE == 0)
            off = ((size_t)(rn * 3 + s) * VV + rv) * (TT * ICC) + rt * ICC + c;
        else
            off = ((size_t)(rn * 3 + s) * TT + rt) * (VV * ICC) + rv * ICC + c;
        dst[off] = val;
    };

#pragma unroll
    for (int tm = 0; tm < 2; tm++) {
        const int rA = row0 + mwarp*32 + tm*16 + g;
        const int rB = rA + 8;
        const int nA = rA/(TT*VV), remA = rA%(TT*VV), tA = remA/VV, vA = remA%VV;
        const int nB = rB/(TT*VV), remB = rB%(TT*VV), tB = remB/VV, vB = remB%VV;
#pragma unroll
        for (int ni = 0; ni < 8; ni++) {
            int jg0 = col0 + nwarp*64 + ni*8 + tig*2;
            float2 b = *(const float2*)(bias + jg0);
            scatter(nA, tA, vA, jg0,     acc[tm][ni][0] + b.x);
            scatter(nA, tA, vA, jg0 + 1, acc[tm][ni][1] + b.y);
            scatter(nB, tB, vB, jg0,     acc[tm][ni][2] + b.x);
            scatter(nB, tB, vB, jg0 + 1, acc[tm][ni][3] + b.y);
        }
    }
}

// ---------------------------------------------------------------------------
// K4 (tensor): GEMM (B x KDIM) @ Wt[KDIM x 256] + bias, fused LN epilogue.
// MODE 0: LN ; 1: gelu(R1+LN) ; 2: gelu(R1+R2+LN).  Wt pre-tf32+pre-permuted.
// BM=64, BN=256, 256 thr, warp grid 2m x 4n, tile m32 x n64; reg-prefetch.
// ---------------------------------------------------------------------------
template<int KDIM, int MODE>
__global__ void __launch_bounds__(256, 2) gemm_ln_tc(
    const float* __restrict__ A, const unsigned* __restrict__ W,
    const float* __restrict__ bias,
    const float* __restrict__ R1, const float* __restrict__ R2,
    float* __restrict__ Out)
{
    __shared__ __align__(16) unsigned As[64][20];
    __shared__ __align__(16) unsigned Ws[16][264];   // 264 % 32 == 8
    __shared__ float red_s[64][4];
    __shared__ float red_q[64][4];
    const int tid  = threadIdx.x;
    const int wid  = tid >> 5, lane = tid & 31;
    const int g    = lane >> 2, tig = lane & 3;
    const int mwarp = wid >> 2, nwarp = wid & 3;
    const size_t row0 = (size_t)blockIdx.x * 64;

    float acc[2][8][4];
#pragma unroll
    for (int tm = 0; tm < 2; tm++)
#pragma unroll
        for (int ni = 0; ni < 8; ni++)
#pragma unroll
            for (int j = 0; j < 4; j++) acc[tm][ni][j] = 0.f;

    const int ar = tid >> 2;                // 0..63
    const int ak = (tid & 3) * 4;           // 0,4,8,12
    const float* Arow = A + (row0 + ar) * KDIM + ak;
    const int lwk = tid >> 4;               // 0..15
    const int lwc = (tid & 15) * 4;         // 0..60
    const unsigned* Wbase = W + (size_t)lwk * 256 + lwc;

    // prologue prefetch (kb = 0)
    float4 pA = *(const float4*)(Arow);
    uint4 pW0 = *(const uint4*)(Wbase);
    uint4 pW1 = *(const uint4*)(Wbase + 64);
    uint4 pW2 = *(const uint4*)(Wbase + 128);
    uint4 pW3 = *(const uint4*)(Wbase + 192);

    for (int kb = 0; kb < KDIM; kb += 16) {
        unsigned* as = &As[ar][ak];
        as[0] = f2tf(pA.x); as[1] = f2tf(pA.y); as[2] = f2tf(pA.z); as[3] = f2tf(pA.w);
        unsigned* ws = &Ws[lwk][lwc];
        *(uint4*)(ws)       = pW0;
        *(uint4*)(ws + 64)  = pW1;
        *(uint4*)(ws + 128) = pW2;
        *(uint4*)(ws + 192) = pW3;
        __syncthreads();
        if (kb + 16 < KDIM) {
            pA = *(const float4*)(Arow + kb + 16);
            const unsigned* wnext = Wbase + (size_t)(kb + 16) * 256;
            pW0 = *(const uint4*)(wnext);
            pW1 = *(const uint4*)(wnext + 64);
            pW2 = *(const uint4*)(wnext + 128);
            pW3 = *(const uint4*)(wnext + 192);
        }
#pragma unroll
        for (int kk = 0; kk < 2; kk++) {
            unsigned af[2][4];
#pragma unroll
            for (int tm = 0; tm < 2; tm++) {
                int rb = mwarp * 32 + tm * 16;
                af[tm][0] = As[rb + g    ][kk*8 + tig];
                af[tm][1] = As[rb + g + 8][kk*8 + tig];
                af[tm][2] = As[rb + g    ][kk*8 + tig + 4];
                af[tm][3] = As[rb + g + 8][kk*8 + tig + 4];
            }
#pragma unroll
            for (int ni = 0; ni < 8; ni++) {
                unsigned b0 = Ws[kk*8 + tig    ][nwarp*64 + ni*8 + g];
                unsigned b1 = Ws[kk*8 + tig + 4][nwarp*64 + ni*8 + g];
                mma16n8k8(acc[0][ni], af[0], b0, b1);
                mma16n8k8(acc[1][ni], af[1], b0, b1);
            }
        }
        __syncthreads();
    }

    // ---- epilogue: bias, cross-warp LN, residual/gelu ----
    float psum[2][2] = {{0.f,0.f},{0.f,0.f}};
    float psq [2][2] = {{0.f,0.f},{0.f,0.f}};
#pragma unroll
    for (int tm = 0; tm < 2; tm++)
#pragma unroll
        for (int ni = 0; ni < 8; ni++) {
            float2 b = *(const float2*)(bias + nwarp*64 + ni*8 + tig*2);
            acc[tm][ni][0] += b.x; acc[tm][ni][1] += b.y;
            acc[tm][ni][2] += b.x; acc[tm][ni][3] += b.y;
            psum[tm][0] += acc[tm][ni][0] + acc[tm][ni][1];
            psq [tm][0] += acc[tm][ni][0]*acc[tm][ni][0] + acc[tm][ni][1]*acc[tm][ni][1];
            psum[tm][1] += acc[tm][ni][2] + acc[tm][ni][3];
            psq [tm][1] += acc[tm][ni][2]*acc[tm][ni][2] + acc[tm][ni][3]*acc[tm][ni][3];
        }
#pragma unroll
    for (int m = 1; m <= 2; m <<= 1)
#pragma unroll
        for (int tm = 0; tm < 2; tm++)
#pragma unroll
            for (int h = 0; h < 2; h++) {
                psum[tm][h] += __shfl_xor_sync(0xffffffffu, psum[tm][h], m);
                psq [tm][h] += __shfl_xor_sync(0xffffffffu, psq [tm][h], m);
            }
    if (tig == 0) {
#pragma unroll
        for (int tm = 0; tm < 2; tm++)
#pragma unroll
            for (int h = 0; h < 2; h++) {
                int lr = mwarp*32 + tm*16 + g + h*8;
                red_s[lr][nwarp] = psum[tm][h];
                red_q[lr][nwarp] = psq [tm][h];
            }
    }
    __syncthreads();

    float mean_[2][2], rstd_[2][2];
#pragma unroll
    for (int tm = 0; tm < 2; tm++)
#pragma unroll
        for (int h = 0; h < 2; h++) {
            int lr = mwarp*32 + tm*16 + g + h*8;
            float s = red_s[lr][0] + red_s[lr][1] + red_s[lr][2] + red_s[lr][3];
            float q = red_q[lr][0] + red_q[lr][1] + red_q[lr][2] + red_q[lr][3];
            float mn = s * (1.f/256.f);
            mean_[tm][h] = mn;
            rstd_[tm][h] = rsqrtf(fmaxf(q * (1.f/256.f) - mn*mn, 0.f) + 1e-5f);
        }

#pragma unroll
    for (int tm = 0; tm < 2; tm++) {
        const size_t rA = row0 + mwarp*32 + tm*16 + g;
        const size_t rB = rA + 8;
#pragma unroll
        for (int ni = 0; ni < 8; ni++) {
            int col = nwarp*64 + ni*8 + tig*2;
            size_t oA = rA * 256 + col;
            size_t oB = rB * 256 + col;
            float lnA0 = (acc[tm][ni][0] - mean_[tm][0]) * rstd_[tm][0];
            float lnA1 = (acc[tm][ni][1] - mean_[tm][0]) * rstd_[tm][0];
            float lnB0 = (acc[tm][ni][2] - mean_[tm][1]) * rstd_[tm][1];
            float lnB1 = (acc[tm][ni][3] - mean_[tm][1]) * rstd_[tm][1];
            float2 o1, o2;
            if (MODE == 0) {
                o1 = make_float2(lnA0, lnA1);
                o2 = make_float2(lnB0, lnB1);
            } else {
                float2 r1a = *(const float2*)(R1 + oA);
                float2 r1b = *(const float2*)(R1 + oB);
                float r2ax = 0.f, r2ay = 0.f, r2bx = 0.f, r2by = 0.f;
                if (MODE == 2) {
                    float2 r2a = *(const float2*)(R2 + oA);
                    float2 r2b = *(const float2*)(R2 + oB);
                    r2ax = r2a.x; r2ay = r2a.y; r2bx = r2b.x; r2by = r2b.y;
                }
                o1 = make_float2(gelu_f(r1a.x + r2ax + lnA0), gelu_f(r1a.y + r2ay + lnA1));
                o2 = make_float2(gelu_f(r1b.x + r2bx + lnB0), gelu_f(r1b.y + r2by + lnB1));
            }
            *(float2*)(Out + oA) = o1;
            *(float2*)(Out + oB) = o2;
        }
    }
}

// ---------------------------------------------------------------------------
// K2: spatial attention scores (fp32 SIMT).
// ---------------------------------------------------------------------------
__global__ void __launch_bounds__(640) att_spatial_kernel(
    const float* __restrict__ Q, const float* __restrict__ K,
    const float* __restrict__ att0, float* __restrict__ ATTS)
{
    __shared__ __align__(16) float qt[25][68];
    __shared__ __align__(16) float kt[25][68];
    __shared__ float sa[25][26];
    const int tid = threadIdx.x;
    const int ns  = blockIdx.x;
    const int s   = ns % 3;
    const size_t base = (size_t)ns * (VV * TT * ICC);
    const int v = tid / 25, u = tid % 25;
    float acc = 0.f;

    for (int t = 0; t < 32; t++) {
        for (int idx = tid; idx < 3200; idx += 640) {
            int isk = (idx >= 1600);
            int i2 = idx - isk * 1600;
            int vv = i2 >> 6, cc = i2 & 63;
            float val = (isk ? K : Q)[base + vv * 2048 + t * 64 + cc];
            if (isk) kt[vv][cc] = val; else qt[vv][cc] = val;
        }
        __syncthreads();
        if (tid < 625) {
#pragma unroll
            for (int c4 = 0; c4 < 16; c4++) {
                float4 q4 = *(const float4*)&qt[v][c4 * 4];
                float4 k4 = *(const float4*)&kt[u][c4 * 4];
                acc += q4.x * k4.x + q4.y * k4.y + q4.z * k4.z + q4.w * k4.w;
            }
        }
        __syncthreads();
    }
    if (tid < 625) sa[v][u] = acc;
    __syncthreads();
    if (tid < 625) {
        float sum = 0.f;
#pragma unroll
        for (int uu = 0; uu < 25; uu++) sum += sa[v][uu];
        ATTS[ns * 625 + v * 25 + u] = acc / sum + att0[s * 625 + v * 25 + u];
    }
}

// ---------------------------------------------------------------------------
// K3: y = einsum('nsvu,ntuc->ntvcs', att, x) -> Y768 (col s*256+c).
// ---------------------------------------------------------------------------
__global__ void __launch_bounds__(256) y_spatial_kernel(
    const float* __restrict__ ATTS, const float* __restrict__ X,
    float* __restrict__ Y768)
{
    __shared__ __align__(16) float at[3][25][28];
    const int tid = threadIdx.x;
    const int nt  = blockIdx.x;
    const int n   = nt >> 5;
    for (int idx = tid; idx < 3 * 25 * 28; idx += 256) ((float*)at)[idx] = 0.f;
    __syncthreads();
    const float* asrc = ATTS + n * (3 * 625);
    for (int idx = tid; idx < 1875; idx += 256) {
        int s = idx / 625, rr = idx % 625;
        at[s][rr / 25][rr % 25] = asrc[idx];
    }
    float xreg[28];
    xreg[25] = xreg[26] = xreg[27] = 0.f;
    const int c = tid;
    const float* xb = X + (size_t)nt * (VV * CC) + c;
#pragma unroll
    for (int u = 0; u < 25; u++) xreg[u] = xb[u * 256];
    __syncthreads();

    for (int v = 0; v < 25; v++) {
        size_t ro = ((size_t)(nt * VV + v)) * 768 + c;
#pragma unroll
        for (int s = 0; s < 3; s++) {
            const float4* a4 = (const float4*)&at[s][v][0];
            float acc = 0.f;
#pragma unroll
            for (int u4 = 0; u4 < 7; u4++) {
                float4 a = a4[u4];
                acc += a.x * xreg[u4 * 4] + a.y * xreg[u4 * 4 + 1]
                     + a.z * xreg[u4 * 4 + 2] + a.w * xreg[u4 * 4 + 3];
            }
            Y768[ro + s * 256] = acc;
        }
    }
}

// ---------------------------------------------------------------------------
// K5: temporal attention (one direction), fp32 SIMT.
// ---------------------------------------------------------------------------
__global__ void __launch_bounds__(64) att_temporal_kernel(
    const float* __restrict__ Q, const float* __restrict__ K,
    float* __restrict__ ATT, int fwd)
{
    __shared__ __align__(16) float qt[32][68];
    __shared__ __align__(16) float kt[32][68];
    const int tid = threadIdx.x;
    const int ns  = blockIdx.x;
    const size_t base = (size_t)ns * (TT * VV * ICC);
    const int ti = tid >> 3, ki = tid & 7;
    float acc[4][4];
#pragma unroll
    for (int i = 0; i < 4; i++)
#pragma unroll
        for (int j = 0; j < 4; j++) acc[i][j] = 0.f;

    const int ltt = tid >> 1;
    const int lcc = (tid & 1) * 32;
    for (int v = 0; v < 25; v++) {
        const float* qsrc = Q + base + ltt * 1600 + v * 64 + lcc;
        const float* ksrc = K + base + ltt * 1600 + v * 64 + lcc;
#pragma unroll
        for (int q8 = 0; q8 < 8; q8++) {
            *(float4*)&qt[ltt][lcc + q8 * 4] = *(const float4*)(qsrc + q8 * 4);
            *(float4*)&kt[ltt][lcc + q8 * 4] = *(const float4*)(ksrc + q8 * 4);
        }
        __syncthreads();
#pragma unroll
        for (int c4 = 0; c4 < 16; c4++) {
            float4 q4[4], k4[4];
#pragma unroll
            for (int i = 0; i < 4; i++) q4[i] = *(const float4*)&qt[ti * 4 + i][c4 * 4];
#pragma unroll
            for (int j = 0; j < 4; j++) k4[j] = *(const float4*)&kt[ki * 4 + j][c4 * 4];
#pragma unroll
            for (int i = 0; i < 4; i++)
#pragma unroll
                for (int j = 0; j < 4; j++)
                    acc[i][j] += q4[i].x * k4[j].x + q4[i].y * k4[j].y
                               + q4[i].z * k4[j].z + q4[i].w * k4[j].w;
        }
        __syncthreads();
    }

#pragma unroll
    for (int i = 0; i < 4; i++) {
        int t = ti * 4 + i;
        float row[4];
        float rsum = 0.f;
#pragma unroll
        for (int j = 0; j < 4; j++) {
            int k = ki * 4 + j;
            bool valid = fwd ? (k <= t) : (k >= t);
            row[j] = valid ? acc[i][j] : 0.f;
            rsum += row[j];
        }
        rsum += __shfl_xor_sync(0xffffffffu, rsum, 1);
        rsum += __shfl_xor_sync(0xffffffffu, rsum, 2);
        rsum += __shfl_xor_sync(0xffffffffu, rsum, 4);
        float inv = 1.f / rsum;
#pragma unroll
        for (int j = 0; j < 4; j++)
            ATT[ns * 1024 + t * 32 + ki * 4 + j] = row[j] * inv;
    }
}

// ---------------------------------------------------------------------------
// K6: z = einsum('nstk,nkvc->ntvcs', a, y) for both directions.
// ---------------------------------------------------------------------------
__global__ void __launch_bounds__(256) z_temporal_kernel(
    const float* __restrict__ AF, const float* __restrict__ AB,
    const float* __restrict__ Y, float* __restrict__ ZF, float* __restrict__ ZB)
{
    __shared__ __align__(16) float af[3][32][32];
    __shared__ __align__(16) float ab[3][32][32];
    const int tid = threadIdx.x;
    const int blk = blockIdx.x;
    const int n = blk / 25, v = blk % 25;
    const float* afs = AF + n * 3072;
    const float* abz = AB + n * 3072;
    for (int idx = tid; idx < 3072; idx += 256) {
        ((float*)af)[idx] = afs[idx];
        ((float*)ab)[idx] = abz[idx];
    }
    float yreg[32];
    const int c = tid;
#pragma unroll
    for (int k = 0; k < 32; k++)
        yreg[k] = Y[((size_t)((n * 32 + k) * 25 + v)) * 256 + c];
    __syncthreads();

    for (int t = 0; t < 32; t++) {
        size_t ro = ((size_t)((n * 32 + t) * 25 + v)) * 768;
#pragma unroll
        for (int s = 0; s < 3; s++) {
            const float4* a4 = (const float4*)&af[s][t][0];
            const float4* b4 = (const float4*)&ab[s][t][0];
            float sf = 0.f, sb = 0.f;
#pragma unroll
            for (int k4 = 0; k4 < 8; k4++) {
                float4 a = a4[k4], b = b4[k4];
                sf += a.x * yreg[k4 * 4] + a.y * yreg[k4 * 4 + 1]
                    + a.z * yreg[k4 * 4 + 2] + a.w * yreg[k4 * 4 + 3];
                sb += b.x * yreg[k4 * 4] + b.y * yreg[k4 * 4 + 1]
                    + b.z * yreg[k4 * 4 + 2] + b.w * yreg[k4 * 4 + 3];
            }
            ZF[ro + s * 256 + c] = sf;
            ZB[ro + s * 256 + c] = sb;
        }
    }
}

// ---------------------------------------------------------------------------
extern "C" void kernel_launch(void* const* d_in, const int* in_sizes, int n_in,
                              void* d_out, int out_size)
{
    (void)in_sizes; (void)n_in; (void)out_size;
    const float* x        = (const float*)d_in[0];
    const float* w_in_s   = (const float*)d_in[1];
    const float* b_in_s   = (const float*)d_in[2];
    const float* att0     = (const float*)d_in[3];
    const float* w_out_s  = (const float*)d_in[4];
    const float* b_out_s  = (const float*)d_in[5];
    const float* w_ff_s   = (const float*)d_in[6];
    const float* b_ff_s   = (const float*)d_in[7];
    const float* w_in_tf  = (const float*)d_in[8];
    const float* b_in_tf  = (const float*)d_in[9];
    const float* w_in_tb  = (const float*)d_in[10];
    const float* b_in_tb  = (const float*)d_in[11];
    const float* w_out_tf = (const float*)d_in[12];
    const float* b_out_tf = (const float*)d_in[13];
    const float* w_out_tb = (const float*)d_in[14];
    const float* b_out_tb = (const float*)d_in[15];
    const float* w_ff_t   = (const float*)d_in[16];
    const float* b_ff_t   = (const float*)d_in[17];
    float* out = (float*)d_out;

    float *QA, *KA, *ATTS, *ATTF, *ATTB, *P768A, *P768B, *Y, *ZFln, *Z;
    unsigned* Wt;
    cudaGetSymbolAddress((void**)&QA,    g_QA);
    cudaGetSymbolAddress((void**)&KA,    g_KA);
    cudaGetSymbolAddress((void**)&ATTS,  g_ATTS);
    cudaGetSymbolAddress((void**)&ATTF,  g_ATTF);
    cudaGetSymbolAddress((void**)&ATTB,  g_ATTB);
    cudaGetSymbolAddress((void**)&P768A, g_P768A);
    cudaGetSymbolAddress((void**)&P768B, g_P768B);
    cudaGetSymbolAddress((void**)&Y,     g_Y);
    cudaGetSymbolAddress((void**)&ZFln,  g_ZFln);
    cudaGetSymbolAddress((void**)&Z,     g_Z);
    cudaGetSymbolAddress((void**)&Wt,    g_Wt);

    const int nblkLN = BROWS / 64;           // 1600
    dim3 gA(BROWS / 128, 3);                 // (800, 3)

    // ---- weight prep (tf32 + permute) ----
    prep_weights<<<dim3(96, 8), 256>>>(w_in_s, w_in_tf, w_in_tb,
                                       w_out_s, w_out_tf, w_out_tb,
                                       w_ff_s, w_ff_t, Wt);

    // ---- spatial block ----
    gemm_act_tc<0><<<gA, 256>>>(x, Wt + WT_IN_S, b_in_s, QA, KA);
    att_spatial_kernel<<<NN * SS, 640>>>(QA, KA, att0, ATTS);
    y_spatial_kernel<<<NN * TT, 256>>>(ATTS, x, P768A);                    // Y768
    gemm_ln_tc<768, 1><<<nblkLN, 256>>>(P768A, Wt + WT_OUT_S, b_out_s, x, nullptr, Y);
    gemm_ln_tc<256, 1><<<nblkLN, 256>>>(Y,     Wt + WT_FF_S,  b_ff_s,  x, nullptr, Y);

    // ---- temporal block (Q/K buffers reused fwd then bwd) ----
    gemm_act_tc<1><<<gA, 256>>>(Y, Wt + WT_IN_TF, b_in_tf, QA, KA);
    att_temporal_kernel<<<NN * SS, 64>>>(QA, KA, ATTF, 1);
    gemm_act_tc<1><<<gA, 256>>>(Y, Wt + WT_IN_TB, b_in_tb, QA, KA);
    att_temporal_kernel<<<NN * SS, 64>>>(QA, KA, ATTB, 0);
    z_temporal_kernel<<<NN * VV, 256>>>(ATTF, ATTB, Y, P768A, P768B);      // Z768F, Z768B
    gemm_ln_tc<768, 0><<<nblkLN, 256>>>(P768A, Wt + WT_OUT_TF, b_out_tf, nullptr, nullptr, ZFln);
    gemm_ln_tc<768, 2><<<nblkLN, 256>>>(P768B, Wt + WT_OUT_TB, b_out_tb, Y, ZFln, Z);
    gemm_ln_tc<256, 1><<<nblkLN, 256>>>(Z,     Wt + WT_FF_T,   b_ff_t,  Y, nullptr, out);
}